// round 9
// baseline (speedup 1.0000x reference)
#include <cuda_runtime.h>
#include <cstdint>
#include <cstddef>

// ---------------------------------------------------------------------------
// Problem constants
// ---------------------------------------------------------------------------
#define BATCH   4096
#define TT      2
#define NTOK    49
#define CDIM    192
#define NHEAD   6
#define HDIM    32

#define M_Q   (BATCH * NTOK)          // 200704
#define M_KV  (BATCH * TT * NTOK)     // 401408

// Scratch (device globals: allocation-free rule)
__device__ float g_q [(size_t)M_Q  * CDIM];
__device__ float g_kv[(size_t)M_KV * 2 * CDIM];
__device__ float g_ao[(size_t)M_KV * CDIM];

// ---------------------------------------------------------------------------
// Helpers
// ---------------------------------------------------------------------------
__device__ __forceinline__ uint32_t f2tf32(float f) {   // round-to-nearest tf32
    uint32_t u;
    asm("cvt.rna.tf32.f32 %0, %1;" : "=r"(u) : "f"(f));
    return u;
}
__device__ __forceinline__ float tfv(float f) { return __uint_as_float(f2tf32(f)); }
__device__ __forceinline__ void mma_tf32(float* d, const uint32_t* a,
                                         uint32_t b0, uint32_t b1) {
    asm volatile(
        "mma.sync.aligned.m16n8k8.row.col.f32.tf32.tf32.f32 "
        "{%0,%1,%2,%3}, {%4,%5,%6,%7}, {%8,%9}, {%0,%1,%2,%3};"
        : "+f"(d[0]), "+f"(d[1]), "+f"(d[2]), "+f"(d[3])
        : "r"(a[0]), "r"(a[1]), "r"(a[2]), "r"(a[3]), "r"(b0), "r"(b1));
}
__device__ __forceinline__ uint32_t smem_u32(const void* p) {
    uint32_t a;
    asm("{ .reg .u64 t; cvta.to.shared.u64 t, %1; cvt.u32.u64 %0, t; }" : "=r"(a) : "l"(p));
    return a;
}
__device__ __forceinline__ void cp16(uint32_t dst, const float* src) {
    asm volatile("cp.async.cg.shared.global [%0], [%1], 16;" :: "r"(dst), "l"(src));
}

// ---------------------------------------------------------------------------
// Tensor-core GEMM via mma.sync tf32.
// 512 threads, CTA tile 128 x 192 (gridDim.y column blocks of 192 for NC=384).
// 16 warps = 4(m) x 4(n), warp tile 32 x 48 (2 x 6 m16n8k8 fragments).
// cp.async double-buffered K chunks of 32; raw fp32 in smem (HW tf32 convert).
// smem rows padded to 36 floats -> conflict-free fragment LDS, 16B-aligned rows.
// ---------------------------------------------------------------------------
#define APADW 36
#define ASZ   (128 * APADW)
#define BSZ   (192 * APADW)
#define GEMM_SMEM ((2 * ASZ + 2 * BSZ) * 4)    // 92160 bytes

template<int NCTOT>
__global__ __launch_bounds__(512)
void gemm_mma(const float* __restrict__ A, const float* __restrict__ W,
              const float* __restrict__ bias, float* __restrict__ out)
{
    extern __shared__ float sm[];
    const uint32_t smb = smem_u32(sm);
    const int tid  = threadIdx.x;
    const int wid  = tid >> 5;
    const int lane = tid & 31;
    const int wm   = wid & 3;          // warp row (4 x 32)
    const int wn   = wid >> 2;         // warp col (4 x 48)
    const int gid  = lane >> 2;
    const int tc   = lane & 3;

    const size_t mbase = (size_t)blockIdx.x * 128;
    const int    nbase = blockIdx.y * 192;
    const float* Ablk = A + mbase * CDIM;
    const float* Wblk = W + (size_t)nbase * CDIM;

    const int ar = tid >> 3;                 // 0..63
    const int ak = (tid & 7) << 2;           // 0,4,..,28

    float acc[2][6][4];
#pragma unroll
    for (int mi = 0; mi < 2; mi++)
#pragma unroll
        for (int ni = 0; ni < 6; ni++)
#pragma unroll
            for (int j = 0; j < 4; j++) acc[mi][ni][j] = 0.f;

    // cp.async one K-chunk (32 floats wide) into stage st
    auto issue = [&](int c, int st) {
        const uint32_t ab = smb + (uint32_t)(st * ASZ) * 4;
        const uint32_t wb = smb + (uint32_t)(2 * ASZ + st * BSZ) * 4;
        const int ko = c * 32;
#pragma unroll
        for (int j = 0; j < 2; j++) {            // A: 128 rows
            int r = ar + j * 64;
            cp16(ab + (uint32_t)(r * APADW + ak) * 4, Ablk + (size_t)r * CDIM + ko + ak);
        }
#pragma unroll
        for (int j = 0; j < 3; j++) {            // W: 192 rows
            int r = ar + j * 64;
            cp16(wb + (uint32_t)(r * APADW + ak) * 4, Wblk + (size_t)r * CDIM + ko + ak);
        }
        asm volatile("cp.async.commit_group;" ::: "memory");
    };

    issue(0, 0);
    asm volatile("cp.async.wait_group 0;" ::: "memory");
    __syncthreads();

#pragma unroll 1
    for (int c = 0; c < 6; c++) {
        const int st = c & 1;
        if (c < 5) issue(c + 1, st ^ 1);     // overlap next copy with compute

        const float* sA = sm + st * ASZ;
        const float* sW = sm + 2 * ASZ + st * BSZ;
#pragma unroll
        for (int kk = 0; kk < 4; kk++) {
            const int k0 = kk * 8;
            uint32_t afr[2][4];
#pragma unroll
            for (int mi = 0; mi < 2; mi++) {
                const int m = wm * 32 + mi * 16 + gid;
                afr[mi][0] = __float_as_uint(sA[(m    ) * APADW + k0 + tc    ]);
                afr[mi][1] = __float_as_uint(sA[(m + 8) * APADW + k0 + tc    ]);
                afr[mi][2] = __float_as_uint(sA[(m    ) * APADW + k0 + tc + 4]);
                afr[mi][3] = __float_as_uint(sA[(m + 8) * APADW + k0 + tc + 4]);
            }
#pragma unroll
            for (int ni = 0; ni < 6; ni++) {
                const int n = wn * 48 + ni * 8 + gid;
                uint32_t b0 = __float_as_uint(sW[n * APADW + k0 + tc    ]);
                uint32_t b1 = __float_as_uint(sW[n * APADW + k0 + tc + 4]);
                mma_tf32(acc[0][ni], afr[0], b0, b1);
                mma_tf32(acc[1][ni], afr[1], b0, b1);
            }
        }
        if (c < 5) {
            asm volatile("cp.async.wait_group 0;" ::: "memory");
            __syncthreads();
        }
    }

    // Epilogue: bias + direct float2 stores
#pragma unroll
    for (int mi = 0; mi < 2; mi++) {
#pragma unroll
        for (int ni = 0; ni < 6; ni++) {
            const size_t row = mbase + wm * 32 + mi * 16 + gid;
            const int    col = nbase + wn * 48 + ni * 8 + tc * 2;
            const float2 bb = *(const float2*)&bias[col];
            float2 r0, r1;
            r0.x = acc[mi][ni][0] + bb.x; r0.y = acc[mi][ni][1] + bb.y;
            r1.x = acc[mi][ni][2] + bb.x; r1.y = acc[mi][ni][3] + bb.y;
            *(float2*)&out[(row    ) * NCTOT + col] = r0;
            *(float2*)&out[(row + 8) * NCTOT + col] = r1;
        }
    }
}

// ---------------------------------------------------------------------------
// Tensor-core attention (unchanged from R8): 2 heads per CTA, warp-local.
// S overlays the Q+K region -> 43.7KB smem/CTA, 5 CTAs/SM.
// ---------------------------------------------------------------------------
#define HPC     2
#define QKV_PAD 36
#define S_PAD   58
#define HEADF2  (3 * NTOK * QKV_PAD)                   // 5292 floats per head
#define ATTN_SMEM ((HPC * HEADF2 + HPC * 169) * 4)     // 43688 bytes

__global__ __launch_bounds__(HPC * 32, 1)
void attn_mma(const float* __restrict__ Q, const float* __restrict__ KV,
              const float* __restrict__ rpb, float* __restrict__ O)
{
    extern __shared__ float sm[];
    const int wid  = threadIdx.x >> 5;
    const int lane = threadIdx.x & 31;
    const int gid  = lane >> 2;
    const int tc   = lane & 3;
    const int bt   = blockIdx.x;
    const int b    = bt >> 1;
    const int h    = blockIdx.y * HPC + wid;

    float* sQ = sm + wid * HEADF2;
    float* sK = sQ + NTOK * QKV_PAD;
    float* sV = sK + NTOK * QKV_PAD;
    float* sS = sQ;                                    // overlay on Q+K
    float* srpb = sm + HPC * HEADF2 + wid * 169;

    for (int i = lane; i < 169; i += 32) srpb[i] = rpb[i * NHEAD + h];

    const float scale = 0.17677669529663687f;
    for (int i = lane; i < NTOK * 8; i += 32) {
        int n = i >> 3, c4 = (i & 7) << 2;
        float4 q = *(const float4*)&Q[((size_t)(b * NTOK + n)) * CDIM + h * HDIM + c4];
        sQ[n * QKV_PAD + c4 + 0] = tfv(q.x * scale);
        sQ[n * QKV_PAD + c4 + 1] = tfv(q.y * scale);
        sQ[n * QKV_PAD + c4 + 2] = tfv(q.z * scale);
        sQ[n * QKV_PAD + c4 + 3] = tfv(q.w * scale);
        size_t kb = (size_t)(bt * NTOK + n) * (2 * CDIM) + h * HDIM + c4;
        float4 k = *(const float4*)&KV[kb];
        sK[n * QKV_PAD + c4 + 0] = tfv(k.x);
        sK[n * QKV_PAD + c4 + 1] = tfv(k.y);
        sK[n * QKV_PAD + c4 + 2] = tfv(k.z);
        sK[n * QKV_PAD + c4 + 3] = tfv(k.w);
        float4 v = *(const float4*)&KV[kb + CDIM];
        sV[n * QKV_PAD + c4 + 0] = tfv(v.x);
        sV[n * QKV_PAD + c4 + 1] = tfv(v.y);
        sV[n * QKV_PAD + c4 + 2] = tfv(v.z);
        sV[n * QKV_PAD + c4 + 3] = tfv(v.w);
    }
    __syncwarp();

    int mr[4][2], nr[7];
#pragma unroll
    for (int mi = 0; mi < 4; mi++) {
        mr[mi][0] = min(16 * mi + gid, 48);
        mr[mi][1] = min(16 * mi + gid + 8, 48);
    }
#pragma unroll
    for (int ni = 0; ni < 7; ni++) nr[ni] = min(8 * ni + gid, 48);

    // ---- S = (Q*scale) K^T ----
    float sf[4][7][4];
#pragma unroll
    for (int mi = 0; mi < 4; mi++)
#pragma unroll
        for (int ni = 0; ni < 7; ni++)
#pragma unroll
            for (int j = 0; j < 4; j++) sf[mi][ni][j] = 0.f;

#pragma unroll
    for (int kk = 0; kk < 4; kk++) {
        const int k0 = kk * 8;
        uint32_t a[4][4];
#pragma unroll
        for (int mi = 0; mi < 4; mi++) {
            a[mi][0] = __float_as_uint(sQ[mr[mi][0] * QKV_PAD + k0 + tc    ]);
            a[mi][1] = __float_as_uint(sQ[mr[mi][1] * QKV_PAD + k0 + tc    ]);
            a[mi][2] = __float_as_uint(sQ[mr[mi][0] * QKV_PAD + k0 + tc + 4]);
            a[mi][3] = __float_as_uint(sQ[mr[mi][1] * QKV_PAD + k0 + tc + 4]);
        }
#pragma unroll
        for (int ni = 0; ni < 7; ni++) {
            uint32_t b0 = __float_as_uint(sK[nr[ni] * QKV_PAD + k0 + tc    ]);
            uint32_t b1 = __float_as_uint(sK[nr[ni] * QKV_PAD + k0 + tc + 4]);
#pragma unroll
            for (int mi = 0; mi < 4; mi++) mma_tf32(sf[mi][ni], a[mi], b0, b1);
        }
    }
    __syncwarp();     // all Q/K fragment reads done before S overlays them

    // Store S (rows < 49 only)
#pragma unroll
    for (int mi = 0; mi < 4; mi++) {
        const int r0 = 16 * mi + gid;
#pragma unroll
        for (int ni = 0; ni < 7; ni++) {
            const int col = 8 * ni + 2 * tc;
            if (r0 < NTOK) {
                sS[r0 * S_PAD + col]     = sf[mi][ni][0];
                sS[r0 * S_PAD + col + 1] = sf[mi][ni][1];
            }
            if (r0 + 8 < NTOK) {
                sS[(r0 + 8) * S_PAD + col]     = sf[mi][ni][2];
                sS[(r0 + 8) * S_PAD + col + 1] = sf[mi][ni][3];
            }
        }
    }
    __syncwarp();

    // ---- softmax (bias folded in), one row per lane ----
#pragma unroll
    for (int rep = 0; rep < 2; rep++) {
        const int n = lane + rep * 32;
        if (n < NTOK) {
            float* row = sS + n * S_PAD;
            const float* bp = srpb + (n / 7) * 13 + (n % 7) + 84;
            float mx = -1e30f;
#pragma unroll
            for (int m = 0; m < NTOK; m++) {
                float v = row[m] + bp[-((m / 7) * 13 + (m % 7))];
                row[m] = v;
                mx = fmaxf(mx, v);
            }
            float sum = 0.f;
#pragma unroll
            for (int m = 0; m < NTOK; m++) {
                float e = __expf(row[m] - mx);
                row[m] = e;
                sum += e;
            }
            const float inv = 1.f / sum;
#pragma unroll
            for (int m = 0; m < NTOK; m++) row[m] = tfv(row[m] * inv);
#pragma unroll
            for (int m = NTOK; m < 56; m++) row[m] = 0.f;   // pad cols -> 0
        }
    }
    __syncwarp();

    // ---- O = P V ----
    float of[4][4][4];
#pragma unroll
    for (int mi = 0; mi < 4; mi++)
#pragma unroll
        for (int nd = 0; nd < 4; nd++)
#pragma unroll
            for (int j = 0; j < 4; j++) of[mi][nd][j] = 0.f;

#pragma unroll
    for (int kk = 0; kk < 7; kk++) {
        const int k0 = kk * 8;
        uint32_t a[4][4];
#pragma unroll
        for (int mi = 0; mi < 4; mi++) {
            a[mi][0] = __float_as_uint(sS[mr[mi][0] * S_PAD + k0 + tc    ]);
            a[mi][1] = __float_as_uint(sS[mr[mi][1] * S_PAD + k0 + tc    ]);
            a[mi][2] = __float_as_uint(sS[mr[mi][0] * S_PAD + k0 + tc + 4]);
            a[mi][3] = __float_as_uint(sS[mr[mi][1] * S_PAD + k0 + tc + 4]);
        }
        const int bm0 = min(k0 + tc, 48);        // P cols >= 49 are zero
        const int bm1 = min(k0 + tc + 4, 48);
#pragma unroll
        for (int nd = 0; nd < 4; nd++) {
            uint32_t b0 = __float_as_uint(sV[bm0 * QKV_PAD + nd * 8 + gid]);
            uint32_t b1 = __float_as_uint(sV[bm1 * QKV_PAD + nd * 8 + gid]);
#pragma unroll
            for (int mi = 0; mi < 4; mi++) mma_tf32(of[mi][nd], a[mi], b0, b1);
        }
    }
#pragma unroll
    for (int mi = 0; mi < 4; mi++) {
        const int r0 = 16 * mi + gid;
#pragma unroll
        for (int nd = 0; nd < 4; nd++) {
            const int col = h * HDIM + nd * 8 + 2 * tc;
            if (r0 < NTOK) {
                float2 o = {of[mi][nd][0], of[mi][nd][1]};
                *(float2*)&O[((size_t)(bt * NTOK + r0)) * CDIM + col] = o;
            }
            if (r0 + 8 < NTOK) {
                float2 o = {of[mi][nd][2], of[mi][nd][3]};
                *(float2*)&O[((size_t)(bt * NTOK + r0 + 8)) * CDIM + col] = o;
            }
        }
    }
}

// ---------------------------------------------------------------------------
// kernel_launch
// ---------------------------------------------------------------------------
extern "C" void kernel_launch(void* const* d_in, const int* in_sizes, int n_in,
                              void* d_out, int out_size)
{
    const float* x      = (const float*)d_in[0];
    const float* memory = (const float*)d_in[1];
    const float* w_q    = (const float*)d_in[2];
    const float* b_q    = (const float*)d_in[3];
    const float* w_kv   = (const float*)d_in[4];
    const float* b_kv   = (const float*)d_in[5];
    const float* w_proj = (const float*)d_in[6];
    const float* b_proj = (const float*)d_in[7];
    const float* rpb    = (const float*)d_in[8];
    float* out = (float*)d_out;

    float *gq, *gkv, *gao;
    cudaGetSymbolAddress((void**)&gq,  g_q);
    cudaGetSymbolAddress((void**)&gkv, g_kv);
    cudaGetSymbolAddress((void**)&gao, g_ao);

    cudaFuncSetAttribute(gemm_mma<192>, cudaFuncAttributeMaxDynamicSharedMemorySize, GEMM_SMEM);
    cudaFuncSetAttribute(gemm_mma<384>, cudaFuncAttributeMaxDynamicSharedMemorySize, GEMM_SMEM);
    cudaFuncSetAttribute(attn_mma, cudaFuncAttributeMaxDynamicSharedMemorySize, ATTN_SMEM);

    // Q projection
    gemm_mma<192><<<dim3(M_Q / 128, 1), 512, GEMM_SMEM>>>(x, w_q, b_q, gq);
    // KV projection (2 column blocks of 192)
    gemm_mma<384><<<dim3(M_KV / 128, 2), 512, GEMM_SMEM>>>(memory, w_kv, b_kv, gkv);
    // Tensor-core attention: 2 heads/CTA, 3 head-pair columns
    attn_mma<<<dim3(BATCH * TT, NHEAD / HPC), HPC * 32, ATTN_SMEM>>>(gq, gkv, rpb, gao);
    // Output projection
    gemm_mma<192><<<dim3(M_KV / 128, 1), 512, GEMM_SMEM>>>(gao, w_proj, b_proj, out);
}

// round 10
// speedup vs baseline: 1.1639x; 1.1639x over previous
#include <cuda_runtime.h>
#include <cuda_fp16.h>
#include <cstdint>
#include <cstddef>

// ---------------------------------------------------------------------------
// Problem constants
// ---------------------------------------------------------------------------
#define BATCH   4096
#define TT      2
#define NTOK    49
#define CDIM    192
#define NHEAD   6
#define HDIM    32

#define M_Q   (BATCH * NTOK)          // 200704
#define M_KV  (BATCH * TT * NTOK)     // 401408

// Scratch (device globals: allocation-free rule)
__device__ float g_q [(size_t)M_Q  * CDIM];
__device__ float g_kv[(size_t)M_KV * 2 * CDIM];
__device__ float g_ao[(size_t)M_KV * CDIM];

// ---------------------------------------------------------------------------
// Helpers
// ---------------------------------------------------------------------------
__device__ __forceinline__ uint32_t f2tf32(float f) {   // round-to-nearest tf32
    uint32_t u;
    asm("cvt.rna.tf32.f32 %0, %1;" : "=r"(u) : "f"(f));
    return u;
}
__device__ __forceinline__ float tfv(float f) { return __uint_as_float(f2tf32(f)); }
__device__ __forceinline__ void mma_tf32(float* d, const uint32_t* a,
                                         uint32_t b0, uint32_t b1) {
    asm volatile(
        "mma.sync.aligned.m16n8k8.row.col.f32.tf32.tf32.f32 "
        "{%0,%1,%2,%3}, {%4,%5,%6,%7}, {%8,%9}, {%0,%1,%2,%3};"
        : "+f"(d[0]), "+f"(d[1]), "+f"(d[2]), "+f"(d[3])
        : "r"(a[0]), "r"(a[1]), "r"(a[2]), "r"(a[3]), "r"(b0), "r"(b1));
}
__device__ __forceinline__ void mma_f16(float* d, const uint32_t* a,
                                        uint32_t b0, uint32_t b1) {
    asm volatile(
        "mma.sync.aligned.m16n8k16.row.col.f32.f16.f16.f32 "
        "{%0,%1,%2,%3}, {%4,%5,%6,%7}, {%8,%9}, {%0,%1,%2,%3};"
        : "+f"(d[0]), "+f"(d[1]), "+f"(d[2]), "+f"(d[3])
        : "r"(a[0]), "r"(a[1]), "r"(a[2]), "r"(a[3]), "r"(b0), "r"(b1));
}
__device__ __forceinline__ uint32_t h2u(float x, float y) {  // rn-packed half2
    __half2 h = __floats2half2_rn(x, y);                     // x -> lo, y -> hi
    return *reinterpret_cast<uint32_t*>(&h);
}

// ---------------------------------------------------------------------------
// Tensor-core GEMM via mma.sync fp16 (f32 accumulate).
// out[m][c] = sum_k A[m][k] * W[c][k] + bias[c]
// 256 threads, CTA tile 128 x 192 (gridDim.y column blocks for NC=384).
// 8 warps = 4(m) x 2(n), warp tile 32 x 96 (2 x 12 m16n8k16 fragments).
// K chunks of 32 (2 k16 steps), double-buffered, LDG->h2(rn)->STS producer.
// smem rows: 40 halves (20 words) -> conflict-free b32 fragment loads.
// ---------------------------------------------------------------------------
#define WROW  20                       // words per smem row (32 halves + pad)
#define AWSZ  (128 * WROW)             // words per A stage
#define WWSZ  (192 * WROW)             // words per W stage
#define GEMM_SMEM ((2 * AWSZ + 2 * WWSZ) * 4)   // 51200 bytes

template<int NCTOT>
__global__ __launch_bounds__(256, 1)
void gemm_mma(const float* __restrict__ A, const float* __restrict__ W,
              const float* __restrict__ bias, float* __restrict__ out)
{
    extern __shared__ uint32_t smw[];
    const int tid  = threadIdx.x;
    const int wid  = tid >> 5;
    const int lane = tid & 31;
    const int wm   = wid & 3;          // warp row (4 x 32)
    const int wn   = wid >> 2;         // warp col (2 x 96)
    const int gid  = lane >> 2;
    const int tc   = lane & 3;

    const size_t mbase = (size_t)blockIdx.x * 128;
    const int    nbase = blockIdx.y * 192;
    const float* Ablk = A + mbase * CDIM;
    const float* Wblk = W + (size_t)nbase * CDIM;

    float acc[2][12][4];
#pragma unroll
    for (int mi = 0; mi < 2; mi++)
#pragma unroll
        for (int ni = 0; ni < 12; ni++)
#pragma unroll
            for (int j = 0; j < 4; j++) acc[mi][ni][j] = 0.f;

    const int ar = tid >> 3;                 // 0..31
    const int ak = (tid & 7) << 2;           // f32/half col 0,4,...,28
    float4 apf[4], wpf[6];

    // Prefetch chunk 0
#pragma unroll
    for (int j = 0; j < 4; j++)
        apf[j] = *(const float4*)(Ablk + (size_t)(ar + j * 32) * CDIM + ak);
#pragma unroll
    for (int j = 0; j < 6; j++)
        wpf[j] = *(const float4*)(Wblk + (size_t)(ar + j * 32) * CDIM + ak);

    // Store chunk 0 -> stage 0 (fp32 -> half2 rn, 8B stores)
    {
        uint32_t* sA = smw;
        uint32_t* sW = smw + 2 * AWSZ;
#pragma unroll
        for (int j = 0; j < 4; j++) {
            int r = ar + j * 32;
            uint2 p = { h2u(apf[j].x, apf[j].y), h2u(apf[j].z, apf[j].w) };
            *(uint2*)&sA[r * WROW + (ak >> 1)] = p;
        }
#pragma unroll
        for (int j = 0; j < 6; j++) {
            int r = ar + j * 32;
            uint2 p = { h2u(wpf[j].x, wpf[j].y), h2u(wpf[j].z, wpf[j].w) };
            *(uint2*)&sW[r * WROW + (ak >> 1)] = p;
        }
    }
    __syncthreads();

#pragma unroll 1
    for (int c = 0; c < 6; c++) {
        const int st = c & 1;
        if (c < 5) {
            const int ko = (c + 1) * 32;
#pragma unroll
            for (int j = 0; j < 4; j++)
                apf[j] = *(const float4*)(Ablk + (size_t)(ar + j * 32) * CDIM + ko + ak);
#pragma unroll
            for (int j = 0; j < 6; j++)
                wpf[j] = *(const float4*)(Wblk + (size_t)(ar + j * 32) * CDIM + ko + ak);
        }

        // Compute on stage st: 2 k16 steps
        {
            const uint32_t* sA = smw + st * AWSZ;
            const uint32_t* sW = smw + 2 * AWSZ + st * WWSZ;
#pragma unroll
            for (int t = 0; t < 2; t++) {
                uint32_t afr[2][4];
#pragma unroll
                for (int mi = 0; mi < 2; mi++) {
                    const int m = wm * 32 + mi * 16 + gid;
                    const int b0 = m * WROW + t * 8 + tc;
                    afr[mi][0] = sA[b0];                 // (m,   k16t lo8)
                    afr[mi][1] = sA[b0 + 8 * WROW];      // (m+8, lo8)
                    afr[mi][2] = sA[b0 + 4];             // (m,   hi8)
                    afr[mi][3] = sA[b0 + 8 * WROW + 4];  // (m+8, hi8)
                }
#pragma unroll
                for (int ni = 0; ni < 12; ni++) {
                    const int n = wn * 96 + ni * 8 + gid;
                    const int nb = n * WROW + t * 8 + tc;
                    uint32_t b0 = sW[nb];
                    uint32_t b1 = sW[nb + 4];
                    mma_f16(acc[0][ni], afr[0], b0, b1);
                    mma_f16(acc[1][ni], afr[1], b0, b1);
                }
            }
        }

        if (c < 5) {
            uint32_t* sA = smw + (st ^ 1) * AWSZ;
            uint32_t* sW = smw + 2 * AWSZ + (st ^ 1) * WWSZ;
#pragma unroll
            for (int j = 0; j < 4; j++) {
                int r = ar + j * 32;
                uint2 p = { h2u(apf[j].x, apf[j].y), h2u(apf[j].z, apf[j].w) };
                *(uint2*)&sA[r * WROW + (ak >> 1)] = p;
            }
#pragma unroll
            for (int j = 0; j < 6; j++) {
                int r = ar + j * 32;
                uint2 p = { h2u(wpf[j].x, wpf[j].y), h2u(wpf[j].z, wpf[j].w) };
                *(uint2*)&sW[r * WROW + (ak >> 1)] = p;
            }
            __syncthreads();
        }
    }

    // Epilogue: bias + direct float2 stores (c frag: rows gid/gid+8, cols 2tc)
#pragma unroll
    for (int mi = 0; mi < 2; mi++) {
#pragma unroll
        for (int ni = 0; ni < 12; ni++) {
            const size_t row = mbase + wm * 32 + mi * 16 + gid;
            const int    col = nbase + wn * 96 + ni * 8 + tc * 2;
            const float2 bb = *(const float2*)&bias[col];
            float2 r0, r1;
            r0.x = acc[mi][ni][0] + bb.x; r0.y = acc[mi][ni][1] + bb.y;
            r1.x = acc[mi][ni][2] + bb.x; r1.y = acc[mi][ni][3] + bb.y;
            *(float2*)&out[(row    ) * NCTOT + col] = r0;
            *(float2*)&out[(row + 8) * NCTOT + col] = r1;
        }
    }
}

// ---------------------------------------------------------------------------
// Tensor-core attention (unchanged from R8, tf32): 2 heads/CTA, warp-local.
// S overlays the Q+K region -> 43.7KB smem/CTA, 5 CTAs/SM.
// ---------------------------------------------------------------------------
#define HPC     2
#define QKV_PAD 36
#define S_PAD   58
#define HEADF2  (3 * NTOK * QKV_PAD)                   // 5292 floats per head
#define ATTN_SMEM ((HPC * HEADF2 + HPC * 169) * 4)     // 43688 bytes

__global__ __launch_bounds__(HPC * 32, 1)
void attn_mma(const float* __restrict__ Q, const float* __restrict__ KV,
              const float* __restrict__ rpb, float* __restrict__ O)
{
    extern __shared__ float sm[];
    const int wid  = threadIdx.x >> 5;
    const int lane = threadIdx.x & 31;
    const int gid  = lane >> 2;
    const int tc   = lane & 3;
    const int bt   = blockIdx.x;
    const int b    = bt >> 1;
    const int h    = blockIdx.y * HPC + wid;

    float* sQ = sm + wid * HEADF2;
    float* sK = sQ + NTOK * QKV_PAD;
    float* sV = sK + NTOK * QKV_PAD;
    float* sS = sQ;                                    // overlay on Q+K
    float* srpb = sm + HPC * HEADF2 + wid * 169;

    for (int i = lane; i < 169; i += 32) srpb[i] = rpb[i * NHEAD + h];

    const float scale = 0.17677669529663687f;
    for (int i = lane; i < NTOK * 8; i += 32) {
        int n = i >> 3, c4 = (i & 7) << 2;
        float4 q = *(const float4*)&Q[((size_t)(b * NTOK + n)) * CDIM + h * HDIM + c4];
        sQ[n * QKV_PAD + c4 + 0] = tfv(q.x * scale);
        sQ[n * QKV_PAD + c4 + 1] = tfv(q.y * scale);
        sQ[n * QKV_PAD + c4 + 2] = tfv(q.z * scale);
        sQ[n * QKV_PAD + c4 + 3] = tfv(q.w * scale);
        size_t kb = (size_t)(bt * NTOK + n) * (2 * CDIM) + h * HDIM + c4;
        float4 k = *(const float4*)&KV[kb];
        sK[n * QKV_PAD + c4 + 0] = tfv(k.x);
        sK[n * QKV_PAD + c4 + 1] = tfv(k.y);
        sK[n * QKV_PAD + c4 + 2] = tfv(k.z);
        sK[n * QKV_PAD + c4 + 3] = tfv(k.w);
        float4 v = *(const float4*)&KV[kb + CDIM];
        sV[n * QKV_PAD + c4 + 0] = tfv(v.x);
        sV[n * QKV_PAD + c4 + 1] = tfv(v.y);
        sV[n * QKV_PAD + c4 + 2] = tfv(v.z);
        sV[n * QKV_PAD + c4 + 3] = tfv(v.w);
    }
    __syncwarp();

    int mr[4][2], nr[7];
#pragma unroll
    for (int mi = 0; mi < 4; mi++) {
        mr[mi][0] = min(16 * mi + gid, 48);
        mr[mi][1] = min(16 * mi + gid + 8, 48);
    }
#pragma unroll
    for (int ni = 0; ni < 7; ni++) nr[ni] = min(8 * ni + gid, 48);

    // ---- S = (Q*scale) K^T ----
    float sf[4][7][4];
#pragma unroll
    for (int mi = 0; mi < 4; mi++)
#pragma unroll
        for (int ni = 0; ni < 7; ni++)
#pragma unroll
            for (int j = 0; j < 4; j++) sf[mi][ni][j] = 0.f;

#pragma unroll
    for (int kk = 0; kk < 4; kk++) {
        const int k0 = kk * 8;
        uint32_t a[4][4];
#pragma unroll
        for (int mi = 0; mi < 4; mi++) {
            a[mi][0] = __float_as_uint(sQ[mr[mi][0] * QKV_PAD + k0 + tc    ]);
            a[mi][1] = __float_as_uint(sQ[mr[mi][1] * QKV_PAD + k0 + tc    ]);
            a[mi][2] = __float_as_uint(sQ[mr[mi][0] * QKV_PAD + k0 + tc + 4]);
            a[mi][3] = __float_as_uint(sQ[mr[mi][1] * QKV_PAD + k0 + tc + 4]);
        }
#pragma unroll
        for (int ni = 0; ni < 7; ni++) {
            uint32_t b0 = __float_as_uint(sK[nr[ni] * QKV_PAD + k0 + tc    ]);
            uint32_t b1 = __float_as_uint(sK[nr[ni] * QKV_PAD + k0 + tc + 4]);
#pragma unroll
            for (int mi = 0; mi < 4; mi++) mma_tf32(sf[mi][ni], a[mi], b0, b1);
        }
    }
    __syncwarp();     // all Q/K fragment reads done before S overlays them

    // Store S (rows < 49 only)
#pragma unroll
    for (int mi = 0; mi < 4; mi++) {
        const int r0 = 16 * mi + gid;
#pragma unroll
        for (int ni = 0; ni < 7; ni++) {
            const int col = 8 * ni + 2 * tc;
            if (r0 < NTOK) {
                sS[r0 * S_PAD + col]     = sf[mi][ni][0];
                sS[r0 * S_PAD + col + 1] = sf[mi][ni][1];
            }
            if (r0 + 8 < NTOK) {
                sS[(r0 + 8) * S_PAD + col]     = sf[mi][ni][2];
                sS[(r0 + 8) * S_PAD + col + 1] = sf[mi][ni][3];
            }
        }
    }
    __syncwarp();

    // ---- softmax (bias folded in), one row per lane ----
#pragma unroll
    for (int rep = 0; rep < 2; rep++) {
        const int n = lane + rep * 32;
        if (n < NTOK) {
            float* row = sS + n * S_PAD;
            const float* bp = srpb + (n / 7) * 13 + (n % 7) + 84;
            float mx = -1e30f;
#pragma unroll
            for (int m = 0; m < NTOK; m++) {
                float v = row[m] + bp[-((m / 7) * 13 + (m % 7))];
                row[m] = v;
                mx = fmaxf(mx, v);
            }
            float sum = 0.f;
#pragma unroll
            for (int m = 0; m < NTOK; m++) {
                float e = __expf(row[m] - mx);
                row[m] = e;
                sum += e;
            }
            const float inv = 1.f / sum;
#pragma unroll
            for (int m = 0; m < NTOK; m++) row[m] = tfv(row[m] * inv);
#pragma unroll
            for (int m = NTOK; m < 56; m++) row[m] = 0.f;   // pad cols -> 0
        }
    }
    __syncwarp();

    // ---- O = P V ----
    float of[4][4][4];
#pragma unroll
    for (int mi = 0; mi < 4; mi++)
#pragma unroll
        for (int nd = 0; nd < 4; nd++)
#pragma unroll
            for (int j = 0; j < 4; j++) of[mi][nd][j] = 0.f;

#pragma unroll
    for (int kk = 0; kk < 7; kk++) {
        const int k0 = kk * 8;
        uint32_t a[4][4];
#pragma unroll
        for (int mi = 0; mi < 4; mi++) {
            a[mi][0] = __float_as_uint(sS[mr[mi][0] * S_PAD + k0 + tc    ]);
            a[mi][1] = __float_as_uint(sS[mr[mi][1] * S_PAD + k0 + tc    ]);
            a[mi][2] = __float_as_uint(sS[mr[mi][0] * S_PAD + k0 + tc + 4]);
            a[mi][3] = __float_as_uint(sS[mr[mi][1] * S_PAD + k0 + tc + 4]);
        }
        const int bm0 = min(k0 + tc, 48);        // P cols >= 49 are zero
        const int bm1 = min(k0 + tc + 4, 48);
#pragma unroll
        for (int nd = 0; nd < 4; nd++) {
            uint32_t b0 = __float_as_uint(sV[bm0 * QKV_PAD + nd * 8 + gid]);
            uint32_t b1 = __float_as_uint(sV[bm1 * QKV_PAD + nd * 8 + gid]);
#pragma unroll
            for (int mi = 0; mi < 4; mi++) mma_tf32(of[mi][nd], a[mi], b0, b1);
        }
    }
#pragma unroll
    for (int mi = 0; mi < 4; mi++) {
        const int r0 = 16 * mi + gid;
#pragma unroll
        for (int nd = 0; nd < 4; nd++) {
            const int col = h * HDIM + nd * 8 + 2 * tc;
            if (r0 < NTOK) {
                float2 o = {of[mi][nd][0], of[mi][nd][1]};
                *(float2*)&O[((size_t)(bt * NTOK + r0)) * CDIM + col] = o;
            }
            if (r0 + 8 < NTOK) {
                float2 o = {of[mi][nd][2], of[mi][nd][3]};
                *(float2*)&O[((size_t)(bt * NTOK + r0 + 8)) * CDIM + col] = o;
            }
        }
    }
}

// ---------------------------------------------------------------------------
// kernel_launch
// ---------------------------------------------------------------------------
extern "C" void kernel_launch(void* const* d_in, const int* in_sizes, int n_in,
                              void* d_out, int out_size)
{
    const float* x      = (const float*)d_in[0];
    const float* memory = (const float*)d_in[1];
    const float* w_q    = (const float*)d_in[2];
    const float* b_q    = (const float*)d_in[3];
    const float* w_kv   = (const float*)d_in[4];
    const float* b_kv   = (const float*)d_in[5];
    const float* w_proj = (const float*)d_in[6];
    const float* b_proj = (const float*)d_in[7];
    const float* rpb    = (const float*)d_in[8];
    float* out = (float*)d_out;

    float *gq, *gkv, *gao;
    cudaGetSymbolAddress((void**)&gq,  g_q);
    cudaGetSymbolAddress((void**)&gkv, g_kv);
    cudaGetSymbolAddress((void**)&gao, g_ao);

    cudaFuncSetAttribute(gemm_mma<192>, cudaFuncAttributeMaxDynamicSharedMemorySize, GEMM_SMEM);
    cudaFuncSetAttribute(gemm_mma<384>, cudaFuncAttributeMaxDynamicSharedMemorySize, GEMM_SMEM);
    cudaFuncSetAttribute(attn_mma, cudaFuncAttributeMaxDynamicSharedMemorySize, ATTN_SMEM);

    // Q projection
    gemm_mma<192><<<dim3(M_Q / 128, 1), 256, GEMM_SMEM>>>(x, w_q, b_q, gq);
    // KV projection (2 column blocks of 192)
    gemm_mma<384><<<dim3(M_KV / 128, 2), 256, GEMM_SMEM>>>(memory, w_kv, b_kv, gkv);
    // Tensor-core attention: 2 heads/CTA, 3 head-pair columns
    attn_mma<<<dim3(BATCH * TT, NHEAD / HPC), HPC * 32, ATTN_SMEM>>>(gq, gkv, rpb, gao);
    // Output projection
    gemm_mma<192><<<dim3(M_KV / 128, 1), 256, GEMM_SMEM>>>(gao, w_proj, b_proj, out);
}

// round 12
// speedup vs baseline: 1.2245x; 1.0521x over previous
#include <cuda_runtime.h>
#include <cuda_fp16.h>
#include <cstdint>
#include <cstddef>

// ---------------------------------------------------------------------------
// Problem constants
// ---------------------------------------------------------------------------
#define BATCH   4096
#define TT      2
#define NTOK    49
#define CDIM    192
#define NHEAD   6
#define HDIM    32

#define M_Q   (BATCH * NTOK)          // 200704
#define M_KV  (BATCH * TT * NTOK)     // 401408

// Scratch (device globals, fp16 intermediates), 16B-aligned for uint4 access
__device__ __align__(16) __half g_q [(size_t)M_Q  * CDIM];          //  77 MB
__device__ __align__(16) __half g_kv[(size_t)M_KV * 2 * CDIM];      // 308 MB
__device__ __align__(16) __half g_ao[(size_t)M_KV * CDIM];          // 154 MB

// ---------------------------------------------------------------------------
// Helpers
// ---------------------------------------------------------------------------
__device__ __forceinline__ void mma_f16(float* d, const uint32_t* a,
                                        uint32_t b0, uint32_t b1) {
    asm volatile(
        "mma.sync.aligned.m16n8k16.row.col.f32.f16.f16.f32 "
        "{%0,%1,%2,%3}, {%4,%5,%6,%7}, {%8,%9}, {%0,%1,%2,%3};"
        : "+f"(d[0]), "+f"(d[1]), "+f"(d[2]), "+f"(d[3])
        : "r"(a[0]), "r"(a[1]), "r"(a[2]), "r"(a[3]), "r"(b0), "r"(b1));
}
__device__ __forceinline__ uint32_t h2u(float x, float y) {  // rn-packed half2
    __half2 h = __floats2half2_rn(x, y);
    return *reinterpret_cast<uint32_t*>(&h);
}

// ---------------------------------------------------------------------------
// Tensor-core GEMM via mma.sync fp16 (f32 accumulate).
// out[m][c] = (sum_k A[m][k] * W[c][k] + bias[c]) * outScale
// 512 threads, CTA tile 128 x 192 (gridDim.y column blocks for NC=384).
// 16 warps = 4(m) x 4(n), warp tile 32 x 48 (2 x 6 m16n8k16 fragments).
// K chunks of 32 halves (2 k16 steps), double-buffered.
// smem rows: 32 halves = 16 words, padded to 20 -> conflict-free b32 loads.
// AHALF: A is fp16 in gmem (raw copy).  OHALF: out is fp16.
// ---------------------------------------------------------------------------
#define WROW  20
#define AWSZ  (128 * WROW)
#define WWSZ  (192 * WROW)
#define GEMM_SMEM ((2 * AWSZ + 2 * WWSZ) * 4)   // 51200 bytes

template<int NCTOT, bool AHALF, bool OHALF>
__global__ __launch_bounds__(512)
void gemm_mma(const void* __restrict__ Ain, const float* __restrict__ W,
              const float* __restrict__ bias, void* __restrict__ outv,
              float outScale)
{
    extern __shared__ uint32_t smw[];
    const int tid  = threadIdx.x;
    const int wid  = tid >> 5;
    const int lane = tid & 31;
    const int wm   = wid & 3;          // warp row (4 x 32)
    const int wn   = wid >> 2;         // warp col (4 x 48)
    const int gid  = lane >> 2;
    const int tc   = lane & 3;

    const size_t mbase = (size_t)blockIdx.x * 128;
    const int    nbase = blockIdx.y * 192;
    const float*  Af = (const float*)Ain + mbase * CDIM;
    const __half* Ah = (const __half*)Ain + mbase * CDIM;
    const float*  Wblk = W + (size_t)nbase * CDIM;

    float acc[2][6][4];
#pragma unroll
    for (int mi = 0; mi < 2; mi++)
#pragma unroll
        for (int ni = 0; ni < 6; ni++)
#pragma unroll
            for (int j = 0; j < 4; j++) acc[mi][ni][j] = 0.f;

    // ---- producer indices ----
    const int ar  = tid >> 3;            // 0..63  (fp32 A rows, W rows)
    const int ak  = (tid & 7) << 2;      // float col 0,4,..,28
    const int ar2 = tid >> 2;            // 0..127 (fp16 A rows)
    const int ag  = tid & 3;             // 8-half group

    float4 apf[2], wpf[3];
    uint4  apfh;

    auto prefetch = [&](int c) {
        const int ko = c * 32;
        if (AHALF) {
            apfh = *(const uint4*)(Ah + (size_t)ar2 * CDIM + ko + ag * 8);
        } else {
#pragma unroll
            for (int j = 0; j < 2; j++)
                apf[j] = *(const float4*)(Af + (size_t)(ar + j * 64) * CDIM + ko + ak);
        }
#pragma unroll
        for (int j = 0; j < 3; j++)
            wpf[j] = *(const float4*)(Wblk + (size_t)(ar + j * 64) * CDIM + ko + ak);
    };
    auto store = [&](int st) {
        uint32_t* sA = smw + st * AWSZ;
        uint32_t* sW = smw + 2 * AWSZ + st * WWSZ;
        if (AHALF) {
            *(uint4*)&sA[ar2 * WROW + ag * 4] = apfh;
        } else {
#pragma unroll
            for (int j = 0; j < 2; j++) {
                int r = ar + j * 64;
                uint2 p = { h2u(apf[j].x, apf[j].y), h2u(apf[j].z, apf[j].w) };
                *(uint2*)&sA[r * WROW + (ak >> 1)] = p;
            }
        }
#pragma unroll
        for (int j = 0; j < 3; j++) {
            int r = ar + j * 64;
            uint2 p = { h2u(wpf[j].x, wpf[j].y), h2u(wpf[j].z, wpf[j].w) };
            *(uint2*)&sW[r * WROW + (ak >> 1)] = p;
        }
    };

    prefetch(0);
    store(0);
    __syncthreads();

#pragma unroll 1
    for (int c = 0; c < 6; c++) {
        const int st = c & 1;
        if (c < 5) prefetch(c + 1);

        const uint32_t* sA = smw + st * AWSZ;
        const uint32_t* sW = smw + 2 * AWSZ + st * WWSZ;
#pragma unroll
        for (int t = 0; t < 2; t++) {
            uint32_t afr[2][4];
#pragma unroll
            for (int mi = 0; mi < 2; mi++) {
                const int m = wm * 32 + mi * 16 + gid;
                const int b0 = m * WROW + t * 8 + tc;
                afr[mi][0] = sA[b0];
                afr[mi][1] = sA[b0 + 8 * WROW];
                afr[mi][2] = sA[b0 + 4];
                afr[mi][3] = sA[b0 + 8 * WROW + 4];
            }
#pragma unroll
            for (int ni = 0; ni < 6; ni++) {
                const int n = wn * 48 + ni * 8 + gid;
                const int nb = n * WROW + t * 8 + tc;
                uint32_t b0 = sW[nb];
                uint32_t b1 = sW[nb + 4];
                mma_f16(acc[0][ni], afr[0], b0, b1);
                mma_f16(acc[1][ni], afr[1], b0, b1);
            }
        }
        if (c < 5) {
            __syncthreads();      // all reads of stage st^1 done (prev iter)
            store(st ^ 1);
            __syncthreads();
        }
    }

    // Epilogue
#pragma unroll
    for (int mi = 0; mi < 2; mi++) {
#pragma unroll
        for (int ni = 0; ni < 6; ni++) {
            const size_t row = mbase + wm * 32 + mi * 16 + gid;
            const int    col = nbase + wn * 48 + ni * 8 + tc * 2;
            const float2 bb = *(const float2*)&bias[col];
            float v0 = (acc[mi][ni][0] + bb.x) * outScale;
            float v1 = (acc[mi][ni][1] + bb.y) * outScale;
            float v2 = (acc[mi][ni][2] + bb.x) * outScale;
            float v3 = (acc[mi][ni][3] + bb.y) * outScale;
            if (OHALF) {
                __half* o = (__half*)outv;
                *(uint32_t*)&o[(row    ) * NCTOT + col] = h2u(v0, v1);
                *(uint32_t*)&o[(row + 8) * NCTOT + col] = h2u(v2, v3);
            } else {
                float* o = (float*)outv;
                float2 r0 = {v0, v1}, r1 = {v2, v3};
                *(float2*)&o[(row    ) * NCTOT + col] = r0;
                *(float2*)&o[(row + 8) * NCTOT + col] = r1;
            }
        }
    }
}

// ---------------------------------------------------------------------------
// fp16 tensor-core attention: 2 heads per CTA (64 threads), warp-local.
// All QK/PV math on m16n8k16 fp16 mma; softmax fp32 in smem.
// V stored transposed (sVt[d][m]) so B-fragment k-pairs are contiguous.
// P (half) overlays the dead Q+K region.  ~49 KB smem/CTA -> 4 CTAs/SM.
// Bias idx separable: ridx = f(n) - f(m) + 84, f(t) = 13*(t/7) + t%7.
// HEADW is a multiple of 4 so every per-head base stays 16B-aligned (R11 bug).
// ---------------------------------------------------------------------------
#define HPC       2
#define QK_STR    20                  // words per sQ/sK row (32 halves + pad)
#define VT_STR    36                  // words per sVt/sP row (64 halves + pad)
#define S_STR     58                  // floats per sS row
#define OFF_K     (NTOK * QK_STR)                 // 980
#define OFF_VT    (2 * NTOK * QK_STR)             // 1960
#define OFF_S     (OFF_VT + HDIM * VT_STR)        // 3112
#define OFF_RPB   (OFF_S + NTOK * S_STR)          // 5954
#define HEADW     (((OFF_RPB + 172) + 3) & ~3)    // 6128 words, 16B-aligned
#define ATTN_SMEM (HPC * HEADW * 4)               // 49024 bytes

__global__ __launch_bounds__(HPC * 32, 1)
void attn_mma(const __half* __restrict__ Q, const __half* __restrict__ KV,
              const float* __restrict__ rpb, __half* __restrict__ O)
{
    extern __shared__ uint32_t smw[];
    const int wid  = threadIdx.x >> 5;
    const int lane = threadIdx.x & 31;
    const int gid  = lane >> 2;
    const int tc   = lane & 3;
    const int bt   = blockIdx.x;
    const int b    = bt >> 1;
    const int h    = blockIdx.y * HPC + wid;

    uint32_t* sQ  = smw + wid * HEADW;
    uint32_t* sK  = sQ + OFF_K;
    uint32_t* sVt = sQ + OFF_VT;
    uint32_t* sP  = sQ;                          // overlay on Q+K (dead post-QK)
    float*    sS  = (float*)(sQ + OFF_S);
    float*    srpb = (float*)(sQ + OFF_RPB);
    __half*   sVtH = (__half*)sVt;

    for (int i = lane; i < 169; i += 32) srpb[i] = rpb[i * NHEAD + h];

    // Zero sVt (pad rows m=49..63 must be 0; garbage could be NaN)
    for (int i = lane; i < HDIM * VT_STR; i += 32) sVt[i] = 0;

    // Load Q, K (raw half copies), V transposed
    for (int i = lane; i < NTOK * 4; i += 32) {
        const int n = i >> 2, g = i & 3;
        *(uint4*)&sQ[n * QK_STR + g * 4] =
            *(const uint4*)&Q[((size_t)(b * NTOK + n)) * CDIM + h * HDIM + g * 8];
        const size_t kb = (size_t)(bt * NTOK + n) * (2 * CDIM) + h * HDIM + g * 8;
        *(uint4*)&sK[n * QK_STR + g * 4] = *(const uint4*)&KV[kb];
        // V: 8 halves (d = g*8..g*8+7) of token n -> sVt[d][n]
        uint4 vv = *(const uint4*)&KV[kb + CDIM];
        const __half* vh = (const __half*)&vv;
#pragma unroll
        for (int j = 0; j < 8; j++)
            sVtH[(g * 8 + j) * (2 * VT_STR) + n] = vh[j];
    }
    __syncwarp();

    int mr[4][2], nr[7];
#pragma unroll
    for (int mi = 0; mi < 4; mi++) {
        mr[mi][0] = min(16 * mi + gid, 48);
        mr[mi][1] = min(16 * mi + gid + 8, 48);
    }
#pragma unroll
    for (int ni = 0; ni < 7; ni++) nr[ni] = min(8 * ni + gid, 48);

    // ---- S = Q K^T  (scale already folded into Q by the Q-proj GEMM) ----
    float sf[4][7][4];
#pragma unroll
    for (int mi = 0; mi < 4; mi++)
#pragma unroll
        for (int ni = 0; ni < 7; ni++)
#pragma unroll
            for (int j = 0; j < 4; j++) sf[mi][ni][j] = 0.f;

#pragma unroll
    for (int t = 0; t < 2; t++) {
        uint32_t a[4][4];
#pragma unroll
        for (int mi = 0; mi < 4; mi++) {
            const int b0 = mr[mi][0] * QK_STR + t * 8 + tc;
            const int b1 = mr[mi][1] * QK_STR + t * 8 + tc;
            a[mi][0] = sQ[b0];
            a[mi][1] = sQ[b1];
            a[mi][2] = sQ[b0 + 4];
            a[mi][3] = sQ[b1 + 4];
        }
#pragma unroll
        for (int ni = 0; ni < 7; ni++) {
            const int nb = nr[ni] * QK_STR + t * 8 + tc;
            uint32_t b0 = sK[nb];
            uint32_t b1 = sK[nb + 4];
#pragma unroll
            for (int mi = 0; mi < 4; mi++) mma_f16(sf[mi][ni], a[mi], b0, b1);
        }
    }
    __syncwarp();

    // Store S fp32 (rows < 49)
#pragma unroll
    for (int mi = 0; mi < 4; mi++) {
        const int r0 = 16 * mi + gid;
#pragma unroll
        for (int ni = 0; ni < 7; ni++) {
            const int col = 8 * ni + 2 * tc;
            if (r0 < NTOK) {
                sS[r0 * S_STR + col]     = sf[mi][ni][0];
                sS[r0 * S_STR + col + 1] = sf[mi][ni][1];
            }
            if (r0 + 8 < NTOK) {
                sS[(r0 + 8) * S_STR + col]     = sf[mi][ni][2];
                sS[(r0 + 8) * S_STR + col + 1] = sf[mi][ni][3];
            }
        }
    }
    __syncwarp();    // Q/K fully consumed; sP may overlay them now

    // ---- softmax (bias folded), one row per lane; write P half2 + zero pad --
#pragma unroll
    for (int rep = 0; rep < 2; rep++) {
        const int n = lane + rep * 32;
        if (n < NTOK) {
            float* row = sS + n * S_STR;
            const float* bp = srpb + (n / 7) * 13 + (n % 7) + 84;
            float mx = -1e30f;
#pragma unroll
            for (int m = 0; m < NTOK; m++) {
                float v = row[m] + bp[-((m / 7) * 13 + (m % 7))];
                row[m] = v;
                mx = fmaxf(mx, v);
            }
            float sum = 0.f;
#pragma unroll
            for (int m = 0; m < NTOK; m++) {
                float e = __expf(row[m] - mx);
                row[m] = e;
                sum += e;
            }
            const float inv = 1.f / sum;
            uint32_t* prow = sP + n * VT_STR;
#pragma unroll
            for (int w = 0; w < 32; w++) {
                float p0 = (2 * w     < NTOK) ? row[2 * w]     * inv : 0.f;
                float p1 = (2 * w + 1 < NTOK) ? row[2 * w + 1] * inv : 0.f;
                prow[w] = h2u(p0, p1);
            }
        }
    }
    __syncwarp();

    // ---- O = P V  (K-dim = 64 padded tokens; pad products are 0*0) ----
    float of[4][4][4];
#pragma unroll
    for (int mi = 0; mi < 4; mi++)
#pragma unroll
        for (int nd = 0; nd < 4; nd++)
#pragma unroll
            for (int j = 0; j < 4; j++) of[mi][nd][j] = 0.f;

#pragma unroll
    for (int t = 0; t < 4; t++) {
        uint32_t a[4][4];
#pragma unroll
        for (int mi = 0; mi < 4; mi++) {
            const int b0 = mr[mi][0] * VT_STR + t * 8 + tc;
            const int b1 = mr[mi][1] * VT_STR + t * 8 + tc;
            a[mi][0] = sP[b0];
            a[mi][1] = sP[b1];
            a[mi][2] = sP[b0 + 4];
            a[mi][3] = sP[b1 + 4];
        }
#pragma unroll
        for (int nd = 0; nd < 4; nd++) {
            const int nb = (nd * 8 + gid) * VT_STR + t * 8 + tc;
            uint32_t b0 = sVt[nb];
            uint32_t b1 = sVt[nb + 4];
#pragma unroll
            for (int mi = 0; mi < 4; mi++) mma_f16(of[mi][nd], a[mi], b0, b1);
        }
    }

    // Store O head slice (half2 words)
#pragma unroll
    for (int mi = 0; mi < 4; mi++) {
        const int r0 = 16 * mi + gid;
#pragma unroll
        for (int nd = 0; nd < 4; nd++) {
            const int col = h * HDIM + nd * 8 + 2 * tc;
            if (r0 < NTOK)
                *(uint32_t*)&O[((size_t)(bt * NTOK + r0)) * CDIM + col] =
                    h2u(of[mi][nd][0], of[mi][nd][1]);
            if (r0 + 8 < NTOK)
                *(uint32_t*)&O[((size_t)(bt * NTOK + r0 + 8)) * CDIM + col] =
                    h2u(of[mi][nd][2], of[mi][nd][3]);
        }
    }
}

// ---------------------------------------------------------------------------
// kernel_launch
// ---------------------------------------------------------------------------
extern "C" void kernel_launch(void* const* d_in, const int* in_sizes, int n_in,
                              void* d_out, int out_size)
{
    const float* x      = (const float*)d_in[0];
    const float* memory = (const float*)d_in[1];
    const float* w_q    = (const float*)d_in[2];
    const float* b_q    = (const float*)d_in[3];
    const float* w_kv   = (const float*)d_in[4];
    const float* b_kv   = (const float*)d_in[5];
    const float* w_proj = (const float*)d_in[6];
    const float* b_proj = (const float*)d_in[7];
    const float* rpb    = (const float*)d_in[8];

    __half *gq, *gkv, *gao;
    cudaGetSymbolAddress((void**)&gq,  g_q);
    cudaGetSymbolAddress((void**)&gkv, g_kv);
    cudaGetSymbolAddress((void**)&gao, g_ao);

    cudaFuncSetAttribute((const void*)gemm_mma<192, false, true>,
                         cudaFuncAttributeMaxDynamicSharedMemorySize, GEMM_SMEM);
    cudaFuncSetAttribute((const void*)gemm_mma<384, false, true>,
                         cudaFuncAttributeMaxDynamicSharedMemorySize, GEMM_SMEM);
    cudaFuncSetAttribute((const void*)gemm_mma<192, true, false>,
                         cudaFuncAttributeMaxDynamicSharedMemorySize, GEMM_SMEM);
    cudaFuncSetAttribute((const void*)attn_mma,
                         cudaFuncAttributeMaxDynamicSharedMemorySize, ATTN_SMEM);

    const float scale = 0.17677669529663687f;   // 32^-0.5, folded into Q

    // Q projection -> fp16, scale folded
    gemm_mma<192, false, true><<<dim3(M_Q / 128, 1), 512, GEMM_SMEM>>>(
        x, w_q, b_q, gq, scale);
    // KV projection -> fp16
    gemm_mma<384, false, true><<<dim3(M_KV / 128, 2), 512, GEMM_SMEM>>>(
        memory, w_kv, b_kv, gkv, 1.0f);
    // fp16 tensor-core attention: 2 heads/CTA
    attn_mma<<<dim3(BATCH * TT, NHEAD / HPC), HPC * 32, ATTN_SMEM>>>(
        gq, gkv, rpb, gao);
    // Output projection: fp16 A -> fp32 out
    gemm_mma<192, true, false><<<dim3(M_KV / 128, 1), 512, GEMM_SMEM>>>(
        gao, w_proj, b_proj, d_out, 1.0f);
}

// round 13
// speedup vs baseline: 1.3624x; 1.1126x over previous
#include <cuda_runtime.h>
#include <cuda_fp16.h>
#include <cstdint>
#include <cstddef>

// ---------------------------------------------------------------------------
// Problem constants
// ---------------------------------------------------------------------------
#define BATCH   4096
#define TT      2
#define NTOK    49
#define CDIM    192
#define NHEAD   6
#define HDIM    32

#define M_Q   (BATCH * NTOK)          // 200704
#define M_KV  (BATCH * TT * NTOK)     // 401408

// Scratch (device globals, fp16 intermediates), 16B-aligned for uint4 access
__device__ __align__(16) __half g_q [(size_t)M_Q  * CDIM];          //  77 MB
__device__ __align__(16) __half g_kv[(size_t)M_KV * 2 * CDIM];      // 308 MB
__device__ __align__(16) __half g_ao[(size_t)M_KV * CDIM];          // 154 MB
// fp16 weights (converted once per launch)
__device__ __align__(16) __half g_wq16 [CDIM * CDIM];
__device__ __align__(16) __half g_wkv16[2 * CDIM * CDIM];
__device__ __align__(16) __half g_wp16 [CDIM * CDIM];

// ---------------------------------------------------------------------------
// Helpers
// ---------------------------------------------------------------------------
__device__ __forceinline__ void mma_f16(float* d, const uint32_t* a,
                                        uint32_t b0, uint32_t b1) {
    asm volatile(
        "mma.sync.aligned.m16n8k16.row.col.f32.f16.f16.f32 "
        "{%0,%1,%2,%3}, {%4,%5,%6,%7}, {%8,%9}, {%0,%1,%2,%3};"
        : "+f"(d[0]), "+f"(d[1]), "+f"(d[2]), "+f"(d[3])
        : "r"(a[0]), "r"(a[1]), "r"(a[2]), "r"(a[3]), "r"(b0), "r"(b1));
}
__device__ __forceinline__ uint32_t h2u(float x, float y) {  // rn-packed half2
    __half2 h = __floats2half2_rn(x, y);
    return *reinterpret_cast<uint32_t*>(&h);
}
__device__ __forceinline__ uint32_t smem_u32(const void* p) {
    uint32_t a;
    asm("{ .reg .u64 t; cvta.to.shared.u64 t, %1; cvt.u32.u64 %0, t; }" : "=r"(a) : "l"(p));
    return a;
}
__device__ __forceinline__ void cp16(uint32_t dst, const void* src) {
    asm volatile("cp.async.cg.shared.global [%0], [%1], 16;" :: "r"(dst), "l"(src));
}
__device__ __forceinline__ void ldsm4(uint32_t* r, uint32_t addr) {
    asm volatile("ldmatrix.sync.aligned.m8n8.x4.shared.b16 {%0,%1,%2,%3}, [%4];"
                 : "=r"(r[0]), "=r"(r[1]), "=r"(r[2]), "=r"(r[3]) : "r"(addr));
}

// ---------------------------------------------------------------------------
// Weight fp32 -> fp16 conversion (once per launch; ~3us)
// ---------------------------------------------------------------------------
__global__ void cvt_w(const float* __restrict__ wq, const float* __restrict__ wkv,
                      const float* __restrict__ wp) {
    const int i = blockIdx.x * blockDim.x + threadIdx.x;
    if (i < CDIM * CDIM)     g_wq16[i] = __float2half_rn(wq[i]);
    if (i < 2 * CDIM * CDIM) g_wkv16[i] = __float2half_rn(wkv[i]);
    if (i < CDIM * CDIM)     g_wp16[i] = __float2half_rn(wp[i]);
}

// ---------------------------------------------------------------------------
// Tensor-core GEMM: mma.sync fp16 + ldmatrix fragments + cp.async weights.
// out[m][c] = (sum_k A[m][k] * W16[c][k] + bias[c]) * outScale
// 512 threads, CTA tile 128 x 192 (gridDim.y column blocks for NC=384).
// 16 warps = 4(m) x 4(n), warp tile 32 x 48.
// K chunks of 64 halves (4 k16 steps), 3 chunks, double-buffered.
// smem rows: 64 halves = 32 words, padded to RSW=36 -> LDSM banks 4r%32, clean.
// ---------------------------------------------------------------------------
#define RSW   36
#define AWSZ  (128 * RSW)              // 4608 words per A stage
#define WWSZ  (192 * RSW)              // 6912 words per W stage
#define GEMM_SMEM ((2 * AWSZ + 2 * WWSZ) * 4)   // 92160 bytes

template<int NCTOT, bool AHALF, bool OHALF>
__global__ __launch_bounds__(512)
void gemm_mma(const void* __restrict__ Ain, const __half* __restrict__ Wh,
              const float* __restrict__ bias, void* __restrict__ outv,
              float outScale)
{
    extern __shared__ uint32_t smw[];
    const uint32_t smb = smem_u32(smw);
    const int tid  = threadIdx.x;
    const int wid  = tid >> 5;
    const int lane = tid & 31;
    const int wm   = wid & 3;          // warp row (4 x 32)
    const int wn   = wid >> 2;         // warp col (4 x 48)
    const int gid  = lane >> 2;
    const int tc   = lane & 3;

    const size_t mbase = (size_t)blockIdx.x * 128;
    const int    nbase = blockIdx.y * 192;
    const float*  Af = (const float*)Ain + mbase * CDIM;
    const __half* Ah = (const __half*)Ain + mbase * CDIM;
    const __half* Wblk = Wh + (size_t)nbase * CDIM;

    const uint32_t stA[2] = { smb, smb + AWSZ * 4 };
    const uint32_t stW[2] = { smb + 2 * AWSZ * 4, smb + (2 * AWSZ + WWSZ) * 4 };

    float acc[2][6][4];
#pragma unroll
    for (int mi = 0; mi < 2; mi++)
#pragma unroll
        for (int ni = 0; ni < 6; ni++)
#pragma unroll
            for (int j = 0; j < 4; j++) acc[mi][ni][j] = 0.f;

    // Producer mapping
    const int prow = tid >> 2;           // 0..127
    const int psub = tid & 3;
    float4 apf[4];                        // fp32 A prefetch (64 floats/row, 16/thread)

    auto issueW = [&](int c, int st) {    // W: 192 rows x 64 halves, cp.async
        const int ko = c * 64;
#pragma unroll
        for (int k = 0; k < 3; k++) {
            const int i = tid + k * 512;
            const int r = i >> 3, g = i & 7;
            cp16(stW[st] + (uint32_t)(r * RSW + g * 4) * 4, Wblk + (size_t)r * CDIM + ko + g * 8);
        }
    };
    auto issueA_h = [&](int c, int st) {  // fp16 A, cp.async (2 x 16B / thread)
        const int ko = c * 64;
        cp16(stA[st] + (uint32_t)(prow * RSW + psub * 4) * 4,
             Ah + (size_t)prow * CDIM + ko + psub * 8);
        cp16(stA[st] + (uint32_t)(prow * RSW + (psub + 4) * 4) * 4,
             Ah + (size_t)prow * CDIM + ko + (psub + 4) * 8);
    };
    auto ldgA_f = [&](int c) {            // fp32 A prefetch to regs
        const int ko = c * 64 + psub * 16;
#pragma unroll
        for (int j = 0; j < 4; j++)
            apf[j] = *(const float4*)(Af + (size_t)prow * CDIM + ko + j * 4);
    };
    auto stsA_f = [&](int st) {           // cvt + store fp32-A prefetch
        uint32_t* sA = smw + (stA[st] - smb) / 4;
#pragma unroll
        for (int j = 0; j < 4; j++) {
            uint2 p = { h2u(apf[j].x, apf[j].y), h2u(apf[j].z, apf[j].w) };
            *(uint2*)&sA[prow * RSW + psub * 8 + j * 2] = p;
        }
    };

    // Chunk 0
    if (AHALF) { issueA_h(0, 0); } else { ldgA_f(0); }
    issueW(0, 0);
    asm volatile("cp.async.commit_group;" ::: "memory");
    if (!AHALF) stsA_f(0);
    asm volatile("cp.async.wait_group 0;" ::: "memory");
    __syncthreads();

    // Per-warp LDSM lane byte offsets
    const uint32_t a_lane = ((uint32_t)(wm * 32 + ((lane >> 3) & 1) * 8 + (lane & 7)) * RSW
                            + (lane >> 4) * 4) * 4;
    const uint32_t b_lane = ((uint32_t)(wn * 48 + (lane >> 4) * 8 + (lane & 7)) * RSW
                            + ((lane >> 3) & 1) * 4) * 4;

#pragma unroll 1
    for (int c = 0; c < 3; c++) {
        const int st = c & 1;
        if (c < 2) {                      // issue next stage
            if (AHALF) issueA_h(c + 1, st ^ 1); else ldgA_f(c + 1);
            issueW(c + 1, st ^ 1);
            asm volatile("cp.async.commit_group;" ::: "memory");
        }

        // Compute: 4 k16 steps
#pragma unroll
        for (int t = 0; t < 4; t++) {
            uint32_t a[2][4], bb[3][4];
#pragma unroll
            for (int mi = 0; mi < 2; mi++)
                ldsm4(a[mi], stA[st] + a_lane + (uint32_t)(mi * 16 * RSW + t * 8) * 4);
#pragma unroll
            for (int p = 0; p < 3; p++)
                ldsm4(bb[p], stW[st] + b_lane + (uint32_t)(p * 16 * RSW + t * 8) * 4);
#pragma unroll
            for (int p = 0; p < 3; p++) {
                mma_f16(acc[0][2 * p],     a[0], bb[p][0], bb[p][1]);
                mma_f16(acc[1][2 * p],     a[1], bb[p][0], bb[p][1]);
                mma_f16(acc[0][2 * p + 1], a[0], bb[p][2], bb[p][3]);
                mma_f16(acc[1][2 * p + 1], a[1], bb[p][2], bb[p][3]);
            }
        }

        if (c < 2) {
            if (!AHALF) stsA_f(st ^ 1);   // stage st^1 free since last sync
            asm volatile("cp.async.wait_group 0;" ::: "memory");
            __syncthreads();
        }
    }

    // Epilogue
#pragma unroll
    for (int mi = 0; mi < 2; mi++) {
#pragma unroll
        for (int ni = 0; ni < 6; ni++) {
            const size_t row = mbase + wm * 32 + mi * 16 + gid;
            const int    col = nbase + wn * 48 + ni * 8 + tc * 2;
            const float2 bb2 = *(const float2*)&bias[col];
            float v0 = (acc[mi][ni][0] + bb2.x) * outScale;
            float v1 = (acc[mi][ni][1] + bb2.y) * outScale;
            float v2 = (acc[mi][ni][2] + bb2.x) * outScale;
            float v3 = (acc[mi][ni][3] + bb2.y) * outScale;
            if (OHALF) {
                __half* o = (__half*)outv;
                *(uint32_t*)&o[(row    ) * NCTOT + col] = h2u(v0, v1);
                *(uint32_t*)&o[(row + 8) * NCTOT + col] = h2u(v2, v3);
            } else {
                float* o = (float*)outv;
                float2 r0 = {v0, v1}, r1 = {v2, v3};
                *(float2*)&o[(row    ) * NCTOT + col] = r0;
                *(float2*)&o[(row + 8) * NCTOT + col] = r1;
            }
        }
    }
}

// ---------------------------------------------------------------------------
// fp16 tensor-core attention (unchanged from R12): 2 heads/CTA, warp-local.
// ---------------------------------------------------------------------------
#define HPC       2
#define QK_STR    20
#define VT_STR    36
#define S_STR     58
#define OFF_K     (NTOK * QK_STR)                 // 980
#define OFF_VT    (2 * NTOK * QK_STR)             // 1960
#define OFF_S     (OFF_VT + HDIM * VT_STR)        // 3112
#define OFF_RPB   (OFF_S + NTOK * S_STR)          // 5954
#define HEADW     (((OFF_RPB + 172) + 3) & ~3)    // 6128 words, 16B-aligned
#define ATTN_SMEM (HPC * HEADW * 4)               // 49024 bytes

__global__ __launch_bounds__(HPC * 32, 1)
void attn_mma(const __half* __restrict__ Q, const __half* __restrict__ KV,
              const float* __restrict__ rpb, __half* __restrict__ O)
{
    extern __shared__ uint32_t smw[];
    const int wid  = threadIdx.x >> 5;
    const int lane = threadIdx.x & 31;
    const int gid  = lane >> 2;
    const int tc   = lane & 3;
    const int bt   = blockIdx.x;
    const int b    = bt >> 1;
    const int h    = blockIdx.y * HPC + wid;

    uint32_t* sQ  = smw + wid * HEADW;
    uint32_t* sK  = sQ + OFF_K;
    uint32_t* sVt = sQ + OFF_VT;
    uint32_t* sP  = sQ;                          // overlay on Q+K
    float*    sS  = (float*)(sQ + OFF_S);
    float*    srpb = (float*)(sQ + OFF_RPB);
    __half*   sVtH = (__half*)sVt;

    for (int i = lane; i < 169; i += 32) srpb[i] = rpb[i * NHEAD + h];
    for (int i = lane; i < HDIM * VT_STR; i += 32) sVt[i] = 0;

    for (int i = lane; i < NTOK * 4; i += 32) {
        const int n = i >> 2, g = i & 3;
        *(uint4*)&sQ[n * QK_STR + g * 4] =
            *(const uint4*)&Q[((size_t)(b * NTOK + n)) * CDIM + h * HDIM + g * 8];
        const size_t kb = (size_t)(bt * NTOK + n) * (2 * CDIM) + h * HDIM + g * 8;
        *(uint4*)&sK[n * QK_STR + g * 4] = *(const uint4*)&KV[kb];
        uint4 vv = *(const uint4*)&KV[kb + CDIM];
        const __half* vh = (const __half*)&vv;
#pragma unroll
        for (int j = 0; j < 8; j++)
            sVtH[(g * 8 + j) * (2 * VT_STR) + n] = vh[j];
    }
    __syncwarp();

    int mr[4][2], nr[7];
#pragma unroll
    for (int mi = 0; mi < 4; mi++) {
        mr[mi][0] = min(16 * mi + gid, 48);
        mr[mi][1] = min(16 * mi + gid + 8, 48);
    }
#pragma unroll
    for (int ni = 0; ni < 7; ni++) nr[ni] = min(8 * ni + gid, 48);

    float sf[4][7][4];
#pragma unroll
    for (int mi = 0; mi < 4; mi++)
#pragma unroll
        for (int ni = 0; ni < 7; ni++)
#pragma unroll
            for (int j = 0; j < 4; j++) sf[mi][ni][j] = 0.f;

#pragma unroll
    for (int t = 0; t < 2; t++) {
        uint32_t a[4][4];
#pragma unroll
        for (int mi = 0; mi < 4; mi++) {
            const int b0 = mr[mi][0] * QK_STR + t * 8 + tc;
            const int b1 = mr[mi][1] * QK_STR + t * 8 + tc;
            a[mi][0] = sQ[b0];
            a[mi][1] = sQ[b1];
            a[mi][2] = sQ[b0 + 4];
            a[mi][3] = sQ[b1 + 4];
        }
#pragma unroll
        for (int ni = 0; ni < 7; ni++) {
            const int nb = nr[ni] * QK_STR + t * 8 + tc;
            uint32_t b0 = sK[nb];
            uint32_t b1 = sK[nb + 4];
#pragma unroll
            for (int mi = 0; mi < 4; mi++) mma_f16(sf[mi][ni], a[mi], b0, b1);
        }
    }
    __syncwarp();

#pragma unroll
    for (int mi = 0; mi < 4; mi++) {
        const int r0 = 16 * mi + gid;
#pragma unroll
        for (int ni = 0; ni < 7; ni++) {
            const int col = 8 * ni + 2 * tc;
            if (r0 < NTOK) {
                sS[r0 * S_STR + col]     = sf[mi][ni][0];
                sS[r0 * S_STR + col + 1] = sf[mi][ni][1];
            }
            if (r0 + 8 < NTOK) {
                sS[(r0 + 8) * S_STR + col]     = sf[mi][ni][2];
                sS[(r0 + 8) * S_STR + col + 1] = sf[mi][ni][3];
            }
        }
    }
    __syncwarp();

#pragma unroll
    for (int rep = 0; rep < 2; rep++) {
        const int n = lane + rep * 32;
        if (n < NTOK) {
            float* row = sS + n * S_STR;
            const float* bp = srpb + (n / 7) * 13 + (n % 7) + 84;
            float mx = -1e30f;
#pragma unroll
            for (int m = 0; m < NTOK; m++) {
                float v = row[m] + bp[-((m / 7) * 13 + (m % 7))];
                row[m] = v;
                mx = fmaxf(mx, v);
            }
            float sum = 0.f;
#pragma unroll
            for (int m = 0; m < NTOK; m++) {
                float e = __expf(row[m] - mx);
                row[m] = e;
                sum += e;
            }
            const float inv = 1.f / sum;
            uint32_t* prow = sP + n * VT_STR;
#pragma unroll
            for (int w = 0; w < 32; w++) {
                float p0 = (2 * w     < NTOK) ? row[2 * w]     * inv : 0.f;
                float p1 = (2 * w + 1 < NTOK) ? row[2 * w + 1] * inv : 0.f;
                prow[w] = h2u(p0, p1);
            }
        }
    }
    __syncwarp();

    float of[4][4][4];
#pragma unroll
    for (int mi = 0; mi < 4; mi++)
#pragma unroll
        for (int nd = 0; nd < 4; nd++)
#pragma unroll
            for (int j = 0; j < 4; j++) of[mi][nd][j] = 0.f;

#pragma unroll
    for (int t = 0; t < 4; t++) {
        uint32_t a[4][4];
#pragma unroll
        for (int mi = 0; mi < 4; mi++) {
            const int b0 = mr[mi][0] * VT_STR + t * 8 + tc;
            const int b1 = mr[mi][1] * VT_STR + t * 8 + tc;
            a[mi][0] = sP[b0];
            a[mi][1] = sP[b1];
            a[mi][2] = sP[b0 + 4];
            a[mi][3] = sP[b1 + 4];
        }
#pragma unroll
        for (int nd = 0; nd < 4; nd++) {
            const int nb = (nd * 8 + gid) * VT_STR + t * 8 + tc;
            uint32_t b0 = sVt[nb];
            uint32_t b1 = sVt[nb + 4];
#pragma unroll
            for (int mi = 0; mi < 4; mi++) mma_f16(of[mi][nd], a[mi], b0, b1);
        }
    }

#pragma unroll
    for (int mi = 0; mi < 4; mi++) {
        const int r0 = 16 * mi + gid;
#pragma unroll
        for (int nd = 0; nd < 4; nd++) {
            const int col = h * HDIM + nd * 8 + 2 * tc;
            if (r0 < NTOK)
                *(uint32_t*)&O[((size_t)(bt * NTOK + r0)) * CDIM + col] =
                    h2u(of[mi][nd][0], of[mi][nd][1]);
            if (r0 + 8 < NTOK)
                *(uint32_t*)&O[((size_t)(bt * NTOK + r0 + 8)) * CDIM + col] =
                    h2u(of[mi][nd][2], of[mi][nd][3]);
        }
    }
}

// ---------------------------------------------------------------------------
// kernel_launch
// ---------------------------------------------------------------------------
extern "C" void kernel_launch(void* const* d_in, const int* in_sizes, int n_in,
                              void* d_out, int out_size)
{
    const float* x      = (const float*)d_in[0];
    const float* memory = (const float*)d_in[1];
    const float* w_q    = (const float*)d_in[2];
    const float* b_q    = (const float*)d_in[3];
    const float* w_kv   = (const float*)d_in[4];
    const float* b_kv   = (const float*)d_in[5];
    const float* w_proj = (const float*)d_in[6];
    const float* b_proj = (const float*)d_in[7];
    const float* rpb    = (const float*)d_in[8];

    __half *gq, *gkv, *gao, *wq16, *wkv16, *wp16;
    cudaGetSymbolAddress((void**)&gq,    g_q);
    cudaGetSymbolAddress((void**)&gkv,   g_kv);
    cudaGetSymbolAddress((void**)&gao,   g_ao);
    cudaGetSymbolAddress((void**)&wq16,  g_wq16);
    cudaGetSymbolAddress((void**)&wkv16, g_wkv16);
    cudaGetSymbolAddress((void**)&wp16,  g_wp16);

    cudaFuncSetAttribute((const void*)gemm_mma<192, false, true>,
                         cudaFuncAttributeMaxDynamicSharedMemorySize, GEMM_SMEM);
    cudaFuncSetAttribute((const void*)gemm_mma<384, false, true>,
                         cudaFuncAttributeMaxDynamicSharedMemorySize, GEMM_SMEM);
    cudaFuncSetAttribute((const void*)gemm_mma<192, true, false>,
                         cudaFuncAttributeMaxDynamicSharedMemorySize, GEMM_SMEM);
    cudaFuncSetAttribute((const void*)attn_mma,
                         cudaFuncAttributeMaxDynamicSharedMemorySize, ATTN_SMEM);

    const float scale = 0.17677669529663687f;   // 32^-0.5, folded into Q

    // Convert weights to fp16 once
    cvt_w<<<(2 * CDIM * CDIM + 255) / 256, 256>>>(w_q, w_kv, w_proj);

    // Q projection -> fp16, scale folded
    gemm_mma<192, false, true><<<dim3(M_Q / 128, 1), 512, GEMM_SMEM>>>(
        x, wq16, b_q, gq, scale);
    // KV projection -> fp16
    gemm_mma<384, false, true><<<dim3(M_KV / 128, 2), 512, GEMM_SMEM>>>(
        memory, wkv16, b_kv, gkv, 1.0f);
    // fp16 tensor-core attention: 2 heads/CTA
    attn_mma<<<dim3(BATCH * TT, NHEAD / HPC), HPC * 32, ATTN_SMEM>>>(
        gq, gkv, rpb, gao);
    // Output projection: fp16 A -> fp32 out
    gemm_mma<192, true, false><<<dim3(M_KV / 128, 1), 512, GEMM_SMEM>>>(
        gao, wp16, b_proj, d_out, 1.0f);
}

// round 14
// speedup vs baseline: 1.5780x; 1.1582x over previous
#include <cuda_runtime.h>
#include <cuda_fp16.h>
#include <cstdint>
#include <cstddef>

// ---------------------------------------------------------------------------
// Problem constants
// ---------------------------------------------------------------------------
#define BATCH   4096
#define TT      2
#define NTOK    49
#define CDIM    192
#define NHEAD   6
#define HDIM    32

#define M_Q   (BATCH * NTOK)          // 200704
#define M_KV  (BATCH * TT * NTOK)     // 401408

// Scratch (device globals, fp16 intermediates), 16B-aligned for uint4 access
__device__ __align__(16) __half g_q [(size_t)M_Q  * CDIM];          //  77 MB
__device__ __align__(16) __half g_kv[(size_t)M_KV * 2 * CDIM];      // 308 MB
__device__ __align__(16) __half g_ao[(size_t)M_KV * CDIM];          // 154 MB
// fp16 weights (converted once per launch)
__device__ __align__(16) __half g_wq16 [CDIM * CDIM];
__device__ __align__(16) __half g_wkv16[2 * CDIM * CDIM];
__device__ __align__(16) __half g_wp16 [CDIM * CDIM];

// ---------------------------------------------------------------------------
// Helpers
// ---------------------------------------------------------------------------
__device__ __forceinline__ void mma_f16(float* d, const uint32_t* a,
                                        uint32_t b0, uint32_t b1) {
    asm volatile(
        "mma.sync.aligned.m16n8k16.row.col.f32.f16.f16.f32 "
        "{%0,%1,%2,%3}, {%4,%5,%6,%7}, {%8,%9}, {%0,%1,%2,%3};"
        : "+f"(d[0]), "+f"(d[1]), "+f"(d[2]), "+f"(d[3])
        : "r"(a[0]), "r"(a[1]), "r"(a[2]), "r"(a[3]), "r"(b0), "r"(b1));
}
__device__ __forceinline__ uint32_t h2u(float x, float y) {  // rn-packed half2
    __half2 h = __floats2half2_rn(x, y);
    return *reinterpret_cast<uint32_t*>(&h);
}
__device__ __forceinline__ uint32_t smem_u32(const void* p) {
    uint32_t a;
    asm("{ .reg .u64 t; cvta.to.shared.u64 t, %1; cvt.u32.u64 %0, t; }" : "=r"(a) : "l"(p));
    return a;
}
__device__ __forceinline__ void cp16(uint32_t dst, const void* src) {
    asm volatile("cp.async.cg.shared.global [%0], [%1], 16;" :: "r"(dst), "l"(src));
}
__device__ __forceinline__ void ldsm4(uint32_t* r, uint32_t addr) {
    asm volatile("ldmatrix.sync.aligned.m8n8.x4.shared.b16 {%0,%1,%2,%3}, [%4];"
                 : "=r"(r[0]), "=r"(r[1]), "=r"(r[2]), "=r"(r[3]) : "r"(addr));
}

// ---------------------------------------------------------------------------
// Weight fp32 -> fp16 conversion (once per launch; ~3us)
// ---------------------------------------------------------------------------
__global__ void cvt_w(const float* __restrict__ wq, const float* __restrict__ wkv,
                      const float* __restrict__ wp) {
    const int i = blockIdx.x * blockDim.x + threadIdx.x;
    if (i < CDIM * CDIM)     g_wq16[i] = __float2half_rn(wq[i]);
    if (i < 2 * CDIM * CDIM) g_wkv16[i] = __float2half_rn(wkv[i]);
    if (i < CDIM * CDIM)     g_wp16[i] = __float2half_rn(wp[i]);
}

// ---------------------------------------------------------------------------
// Tensor-core GEMM (unchanged from R13): mma.sync fp16 + ldmatrix + cp.async.
// ---------------------------------------------------------------------------
#define RSW   36
#define AWSZ  (128 * RSW)
#define WWSZ  (192 * RSW)
#define GEMM_SMEM ((2 * AWSZ + 2 * WWSZ) * 4)   // 92160 bytes

template<int NCTOT, bool AHALF, bool OHALF>
__global__ __launch_bounds__(512)
void gemm_mma(const void* __restrict__ Ain, const __half* __restrict__ Wh,
              const float* __restrict__ bias, void* __restrict__ outv,
              float outScale)
{
    extern __shared__ uint32_t smw[];
    const uint32_t smb = smem_u32(smw);
    const int tid  = threadIdx.x;
    const int wid  = tid >> 5;
    const int lane = tid & 31;
    const int wm   = wid & 3;
    const int wn   = wid >> 2;
    const int gid  = lane >> 2;
    const int tc   = lane & 3;

    const size_t mbase = (size_t)blockIdx.x * 128;
    const int    nbase = blockIdx.y * 192;
    const float*  Af = (const float*)Ain + mbase * CDIM;
    const __half* Ah = (const __half*)Ain + mbase * CDIM;
    const __half* Wblk = Wh + (size_t)nbase * CDIM;

    const uint32_t stA[2] = { smb, smb + AWSZ * 4 };
    const uint32_t stW[2] = { smb + 2 * AWSZ * 4, smb + (2 * AWSZ + WWSZ) * 4 };

    float acc[2][6][4];
#pragma unroll
    for (int mi = 0; mi < 2; mi++)
#pragma unroll
        for (int ni = 0; ni < 6; ni++)
#pragma unroll
            for (int j = 0; j < 4; j++) acc[mi][ni][j] = 0.f;

    const int prow = tid >> 2;
    const int psub = tid & 3;
    float4 apf[4];

    auto issueW = [&](int c, int st) {
        const int ko = c * 64;
#pragma unroll
        for (int k = 0; k < 3; k++) {
            const int i = tid + k * 512;
            const int r = i >> 3, g = i & 7;
            cp16(stW[st] + (uint32_t)(r * RSW + g * 4) * 4, Wblk + (size_t)r * CDIM + ko + g * 8);
        }
    };
    auto issueA_h = [&](int c, int st) {
        const int ko = c * 64;
        cp16(stA[st] + (uint32_t)(prow * RSW + psub * 4) * 4,
             Ah + (size_t)prow * CDIM + ko + psub * 8);
        cp16(stA[st] + (uint32_t)(prow * RSW + (psub + 4) * 4) * 4,
             Ah + (size_t)prow * CDIM + ko + (psub + 4) * 8);
    };
    auto ldgA_f = [&](int c) {
        const int ko = c * 64 + psub * 16;
#pragma unroll
        for (int j = 0; j < 4; j++)
            apf[j] = *(const float4*)(Af + (size_t)prow * CDIM + ko + j * 4);
    };
    auto stsA_f = [&](int st) {
        uint32_t* sA = smw + (stA[st] - smb) / 4;
#pragma unroll
        for (int j = 0; j < 4; j++) {
            uint2 p = { h2u(apf[j].x, apf[j].y), h2u(apf[j].z, apf[j].w) };
            *(uint2*)&sA[prow * RSW + psub * 8 + j * 2] = p;
        }
    };

    if (AHALF) { issueA_h(0, 0); } else { ldgA_f(0); }
    issueW(0, 0);
    asm volatile("cp.async.commit_group;" ::: "memory");
    if (!AHALF) stsA_f(0);
    asm volatile("cp.async.wait_group 0;" ::: "memory");
    __syncthreads();

    const uint32_t a_lane = ((uint32_t)(wm * 32 + ((lane >> 3) & 1) * 8 + (lane & 7)) * RSW
                            + (lane >> 4) * 4) * 4;
    const uint32_t b_lane = ((uint32_t)(wn * 48 + (lane >> 4) * 8 + (lane & 7)) * RSW
                            + ((lane >> 3) & 1) * 4) * 4;

#pragma unroll 1
    for (int c = 0; c < 3; c++) {
        const int st = c & 1;
        if (c < 2) {
            if (AHALF) issueA_h(c + 1, st ^ 1); else ldgA_f(c + 1);
            issueW(c + 1, st ^ 1);
            asm volatile("cp.async.commit_group;" ::: "memory");
        }
#pragma unroll
        for (int t = 0; t < 4; t++) {
            uint32_t a[2][4], bb[3][4];
#pragma unroll
            for (int mi = 0; mi < 2; mi++)
                ldsm4(a[mi], stA[st] + a_lane + (uint32_t)(mi * 16 * RSW + t * 8) * 4);
#pragma unroll
            for (int p = 0; p < 3; p++)
                ldsm4(bb[p], stW[st] + b_lane + (uint32_t)(p * 16 * RSW + t * 8) * 4);
#pragma unroll
            for (int p = 0; p < 3; p++) {
                mma_f16(acc[0][2 * p],     a[0], bb[p][0], bb[p][1]);
                mma_f16(acc[1][2 * p],     a[1], bb[p][0], bb[p][1]);
                mma_f16(acc[0][2 * p + 1], a[0], bb[p][2], bb[p][3]);
                mma_f16(acc[1][2 * p + 1], a[1], bb[p][2], bb[p][3]);
            }
        }
        if (c < 2) {
            if (!AHALF) stsA_f(st ^ 1);
            asm volatile("cp.async.wait_group 0;" ::: "memory");
            __syncthreads();
        }
    }

#pragma unroll
    for (int mi = 0; mi < 2; mi++) {
#pragma unroll
        for (int ni = 0; ni < 6; ni++) {
            const size_t row = mbase + wm * 32 + mi * 16 + gid;
            const int    col = nbase + wn * 48 + ni * 8 + tc * 2;
            const float2 bb2 = *(const float2*)&bias[col];
            float v0 = (acc[mi][ni][0] + bb2.x) * outScale;
            float v1 = (acc[mi][ni][1] + bb2.y) * outScale;
            float v2 = (acc[mi][ni][2] + bb2.x) * outScale;
            float v3 = (acc[mi][ni][3] + bb2.y) * outScale;
            if (OHALF) {
                __half* o = (__half*)outv;
                *(uint32_t*)&o[(row    ) * NCTOT + col] = h2u(v0, v1);
                *(uint32_t*)&o[(row + 8) * NCTOT + col] = h2u(v2, v3);
            } else {
                float* o = (float*)outv;
                float2 r0 = {v0, v1}, r1 = {v2, v3};
                *(float2*)&o[(row    ) * NCTOT + col] = r0;
                *(float2*)&o[(row + 8) * NCTOT + col] = r1;
            }
        }
    }
}

// ---------------------------------------------------------------------------
// fp16 attention with REGISTER-RESIDENT softmax: 2 heads/CTA, warp-local.
// S fragments never touch smem; QK output fragments are re-used directly as
// PV A-fragments (col group ni=2t -> a0/a1, ni=2t+1 -> a2/a3; ni=7 -> zeros).
// Row max/sum via butterfly shuffles over the tc bits (lanes 0-1 of lane id).
// smem/head: Q(980) + K(980) + Vt(1152) + rpb(172) = 3284 words = 13.1 KB.
// ---------------------------------------------------------------------------
#define HPC       2
#define QK_STR    20
#define VT_STR    36
#define OFF_K     (NTOK * QK_STR)                 // 980
#define OFF_VT    (2 * NTOK * QK_STR)             // 1960
#define OFF_RPB   (OFF_VT + HDIM * VT_STR)        // 3112
#define HEADW     (OFF_RPB + 172)                 // 3284 words (16B-aligned)
#define ATTN_SMEM (HPC * HEADW * 4)               // 26272 bytes

__global__ __launch_bounds__(HPC * 32)
void attn_mma(const __half* __restrict__ Q, const __half* __restrict__ KV,
              const float* __restrict__ rpb, __half* __restrict__ O)
{
    extern __shared__ uint32_t smw[];
    const int wid  = threadIdx.x >> 5;
    const int lane = threadIdx.x & 31;
    const int gid  = lane >> 2;
    const int tc   = lane & 3;
    const int bt   = blockIdx.x;
    const int b    = bt >> 1;
    const int h    = blockIdx.y * HPC + wid;

    uint32_t* sQ  = smw + wid * HEADW;
    uint32_t* sK  = sQ + OFF_K;
    uint32_t* sVt = sQ + OFF_VT;
    float*    srpb = (float*)(sQ + OFF_RPB);
    __half*   sVtH = (__half*)sVt;

    for (int i = lane; i < 169; i += 32) srpb[i] = rpb[i * NHEAD + h];
    for (int i = lane; i < HDIM * VT_STR; i += 32) sVt[i] = 0;   // pad tokens -> 0

    for (int i = lane; i < NTOK * 4; i += 32) {
        const int n = i >> 2, g = i & 3;
        *(uint4*)&sQ[n * QK_STR + g * 4] =
            *(const uint4*)&Q[((size_t)(b * NTOK + n)) * CDIM + h * HDIM + g * 8];
        const size_t kb = (size_t)(bt * NTOK + n) * (2 * CDIM) + h * HDIM + g * 8;
        *(uint4*)&sK[n * QK_STR + g * 4] = *(const uint4*)&KV[kb];
        uint4 vv = *(const uint4*)&KV[kb + CDIM];
        const __half* vh = (const __half*)&vv;
#pragma unroll
        for (int j = 0; j < 8; j++)
            sVtH[(g * 8 + j) * (2 * VT_STR) + n] = vh[j];
    }
    __syncwarp();

    int mr[4][2], nr[7];
#pragma unroll
    for (int mi = 0; mi < 4; mi++) {
        mr[mi][0] = min(16 * mi + gid, 48);
        mr[mi][1] = min(16 * mi + gid + 8, 48);
    }
#pragma unroll
    for (int ni = 0; ni < 7; ni++) nr[ni] = min(8 * ni + gid, 48);

    // ---- S = Q K^T (scale pre-folded into Q) ----
    float sf[4][7][4];
#pragma unroll
    for (int mi = 0; mi < 4; mi++)
#pragma unroll
        for (int ni = 0; ni < 7; ni++)
#pragma unroll
            for (int j = 0; j < 4; j++) sf[mi][ni][j] = 0.f;

#pragma unroll
    for (int t = 0; t < 2; t++) {
        uint32_t a[4][4];
#pragma unroll
        for (int mi = 0; mi < 4; mi++) {
            const int b0 = mr[mi][0] * QK_STR + t * 8 + tc;
            const int b1 = mr[mi][1] * QK_STR + t * 8 + tc;
            a[mi][0] = sQ[b0];
            a[mi][1] = sQ[b1];
            a[mi][2] = sQ[b0 + 4];
            a[mi][3] = sQ[b1 + 4];
        }
#pragma unroll
        for (int ni = 0; ni < 7; ni++) {
            const int nb = nr[ni] * QK_STR + t * 8 + tc;
            uint32_t b0 = sK[nb];
            uint32_t b1 = sK[nb + 4];
#pragma unroll
            for (int mi = 0; mi < 4; mi++) mma_f16(sf[mi][ni], a[mi], b0, b1);
        }
    }

    // ---- register softmax + pack to PV A-fragments ----
    uint32_t pf[4][4][4];
#pragma unroll
    for (int mi = 0; mi < 4; mi++) {
#pragma unroll
        for (int jp = 0; jp < 2; jp++) {
            const int n = 16 * mi + 8 * jp + gid;        // this row
            const bool vrow = (n < NTOK);
            const int fn = 13 * (n / 7) + (n % 7);
            float vv[7][2];
            float mx = -1e30f;
#pragma unroll
            for (int ni = 0; ni < 7; ni++) {
#pragma unroll
                for (int jc = 0; jc < 2; jc++) {
                    const int m = 8 * ni + 2 * tc + jc;
                    float v = sf[mi][ni][jp * 2 + jc];
                    if (vrow && m < NTOK) {
                        const int fm = 13 * (m / 7) + (m % 7);
                        v += srpb[fn - fm + 84];
                    } else {
                        v = -1e30f;
                    }
                    vv[ni][jc] = v;
                    mx = fmaxf(mx, v);
                }
            }
            mx = fmaxf(mx, __shfl_xor_sync(0xffffffffu, mx, 1));
            mx = fmaxf(mx, __shfl_xor_sync(0xffffffffu, mx, 2));
            float sum = 0.f;
#pragma unroll
            for (int ni = 0; ni < 7; ni++)
#pragma unroll
                for (int jc = 0; jc < 2; jc++) {
                    float e = __expf(vv[ni][jc] - mx);
                    vv[ni][jc] = e;
                    sum += e;
                }
            sum += __shfl_xor_sync(0xffffffffu, sum, 1);
            sum += __shfl_xor_sync(0xffffffffu, sum, 2);
            const float inv = vrow ? (1.f / sum) : 0.f;
#pragma unroll
            for (int t = 0; t < 4; t++) {
                pf[mi][t][jp] = h2u(vv[2 * t][0] * inv, vv[2 * t][1] * inv);
                pf[mi][t][2 + jp] = (2 * t + 1 < 7)
                    ? h2u(vv[2 * t + 1][0] * inv, vv[2 * t + 1][1] * inv) : 0u;
            }
        }
    }

    // ---- O = P V (K = 64 padded tokens; P pad cols and V pad rows are 0) ----
    float of[4][4][4];
#pragma unroll
    for (int mi = 0; mi < 4; mi++)
#pragma unroll
        for (int nd = 0; nd < 4; nd++)
#pragma unroll
            for (int j = 0; j < 4; j++) of[mi][nd][j] = 0.f;

#pragma unroll
    for (int t = 0; t < 4; t++) {
#pragma unroll
        for (int nd = 0; nd < 4; nd++) {
            const int nb = (nd * 8 + gid) * VT_STR + t * 8 + tc;
            uint32_t b0 = sVt[nb];
            uint32_t b1 = sVt[nb + 4];
#pragma unroll
            for (int mi = 0; mi < 4; mi++) mma_f16(of[mi][nd], pf[mi][t], b0, b1);
        }
    }

#pragma unroll
    for (int mi = 0; mi < 4; mi++) {
        const int r0 = 16 * mi + gid;
#pragma unroll
        for (int nd = 0; nd < 4; nd++) {
            const int col = h * HDIM + nd * 8 + 2 * tc;
            if (r0 < NTOK)
                *(uint32_t*)&O[((size_t)(bt * NTOK + r0)) * CDIM + col] =
                    h2u(of[mi][nd][0], of[mi][nd][1]);
            if (r0 + 8 < NTOK)
                *(uint32_t*)&O[((size_t)(bt * NTOK + r0 + 8)) * CDIM + col] =
                    h2u(of[mi][nd][2], of[mi][nd][3]);
        }
    }
}

// ---------------------------------------------------------------------------
// kernel_launch
// ---------------------------------------------------------------------------
extern "C" void kernel_launch(void* const* d_in, const int* in_sizes, int n_in,
                              void* d_out, int out_size)
{
    const float* x      = (const float*)d_in[0];
    const float* memory = (const float*)d_in[1];
    const float* w_q    = (const float*)d_in[2];
    const float* b_q    = (const float*)d_in[3];
    const float* w_kv   = (const float*)d_in[4];
    const float* b_kv   = (const float*)d_in[5];
    const float* w_proj = (const float*)d_in[6];
    const float* b_proj = (const float*)d_in[7];
    const float* rpb    = (const float*)d_in[8];

    __half *gq, *gkv, *gao, *wq16, *wkv16, *wp16;
    cudaGetSymbolAddress((void**)&gq,    g_q);
    cudaGetSymbolAddress((void**)&gkv,   g_kv);
    cudaGetSymbolAddress((void**)&gao,   g_ao);
    cudaGetSymbolAddress((void**)&wq16,  g_wq16);
    cudaGetSymbolAddress((void**)&wkv16, g_wkv16);
    cudaGetSymbolAddress((void**)&wp16,  g_wp16);

    cudaFuncSetAttribute((const void*)gemm_mma<192, false, true>,
                         cudaFuncAttributeMaxDynamicSharedMemorySize, GEMM_SMEM);
    cudaFuncSetAttribute((const void*)gemm_mma<384, false, true>,
                         cudaFuncAttributeMaxDynamicSharedMemorySize, GEMM_SMEM);
    cudaFuncSetAttribute((const void*)gemm_mma<192, true, false>,
                         cudaFuncAttributeMaxDynamicSharedMemorySize, GEMM_SMEM);
    cudaFuncSetAttribute((const void*)attn_mma,
                         cudaFuncAttributeMaxDynamicSharedMemorySize, ATTN_SMEM);

    const float scale = 0.17677669529663687f;   // 32^-0.5, folded into Q

    cvt_w<<<(2 * CDIM * CDIM + 255) / 256, 256>>>(w_q, w_kv, w_proj);

    gemm_mma<192, false, true><<<dim3(M_Q / 128, 1), 512, GEMM_SMEM>>>(
        x, wq16, b_q, gq, scale);
    gemm_mma<384, false, true><<<dim3(M_KV / 128, 2), 512, GEMM_SMEM>>>(
        memory, wkv16, b_kv, gkv, 1.0f);
    attn_mma<<<dim3(BATCH * TT, NHEAD / HPC), HPC * 32, ATTN_SMEM>>>(
        gq, gkv, rpb, gao);
    gemm_mma<192, true, false><<<dim3(M_KV / 128, 1), 512, GEMM_SMEM>>>(
        gao, wp16, b_proj, d_out, 1.0f);
}

// round 15
// speedup vs baseline: 1.6043x; 1.0167x over previous
#include <cuda_runtime.h>
#include <cuda_fp16.h>
#include <cstdint>
#include <cstddef>

// ---------------------------------------------------------------------------
// Problem constants
// ---------------------------------------------------------------------------
#define BATCH   4096
#define TT      2
#define NTOK    49
#define CDIM    192
#define NHEAD   6
#define HDIM    32

#define M_Q   (BATCH * NTOK)          // 200704
#define M_KV  (BATCH * TT * NTOK)     // 401408

// Scratch (device globals, fp16 intermediates), 16B-aligned for uint4 access
__device__ __align__(16) __half g_q [(size_t)M_Q  * CDIM];          //  77 MB
__device__ __align__(16) __half g_kv[(size_t)M_KV * 2 * CDIM];      // 308 MB
__device__ __align__(16) __half g_ao[(size_t)M_KV * CDIM];          // 154 MB
// fp16 weights (converted once per launch)
__device__ __align__(16) __half g_wq16 [CDIM * CDIM];
__device__ __align__(16) __half g_wkv16[2 * CDIM * CDIM];
__device__ __align__(16) __half g_wp16 [CDIM * CDIM];

// ---------------------------------------------------------------------------
// Helpers
// ---------------------------------------------------------------------------
__device__ __forceinline__ void mma_f16(float* d, const uint32_t* a,
                                        uint32_t b0, uint32_t b1) {
    asm volatile(
        "mma.sync.aligned.m16n8k16.row.col.f32.f16.f16.f32 "
        "{%0,%1,%2,%3}, {%4,%5,%6,%7}, {%8,%9}, {%0,%1,%2,%3};"
        : "+f"(d[0]), "+f"(d[1]), "+f"(d[2]), "+f"(d[3])
        : "r"(a[0]), "r"(a[1]), "r"(a[2]), "r"(a[3]), "r"(b0), "r"(b1));
}
__device__ __forceinline__ uint32_t h2u(float x, float y) {  // rn-packed half2
    __half2 h = __floats2half2_rn(x, y);
    return *reinterpret_cast<uint32_t*>(&h);
}
__device__ __forceinline__ uint32_t smem_u32(const void* p) {
    uint32_t a;
    asm("{ .reg .u64 t; cvta.to.shared.u64 t, %1; cvt.u32.u64 %0, t; }" : "=r"(a) : "l"(p));
    return a;
}
__device__ __forceinline__ void cp16(uint32_t dst, const void* src) {
    asm volatile("cp.async.cg.shared.global [%0], [%1], 16;" :: "r"(dst), "l"(src));
}
__device__ __forceinline__ void ldsm4(uint32_t* r, uint32_t addr) {
    asm volatile("ldmatrix.sync.aligned.m8n8.x4.shared.b16 {%0,%1,%2,%3}, [%4];"
                 : "=r"(r[0]), "=r"(r[1]), "=r"(r[2]), "=r"(r[3]) : "r"(addr));
}
__device__ __forceinline__ void ldsm2(uint32_t* r, uint32_t addr) {
    asm volatile("ldmatrix.sync.aligned.m8n8.x2.shared.b16 {%0,%1}, [%2];"
                 : "=r"(r[0]), "=r"(r[1]) : "r"(addr));
}
__device__ __forceinline__ void ldsm4t(uint32_t* r, uint32_t addr) {
    asm volatile("ldmatrix.sync.aligned.m8n8.x4.trans.shared.b16 {%0,%1,%2,%3}, [%4];"
                 : "=r"(r[0]), "=r"(r[1]), "=r"(r[2]), "=r"(r[3]) : "r"(addr));
}

// ---------------------------------------------------------------------------
// Weight fp32 -> fp16 conversion (once per launch; ~3us)
// ---------------------------------------------------------------------------
__global__ void cvt_w(const float* __restrict__ wq, const float* __restrict__ wkv,
                      const float* __restrict__ wp) {
    const int i = blockIdx.x * blockDim.x + threadIdx.x;
    if (i < CDIM * CDIM)     g_wq16[i] = __float2half_rn(wq[i]);
    if (i < 2 * CDIM * CDIM) g_wkv16[i] = __float2half_rn(wkv[i]);
    if (i < CDIM * CDIM)     g_wp16[i] = __float2half_rn(wp[i]);
}

// ---------------------------------------------------------------------------
// Tensor-core GEMM (unchanged from R13): mma.sync fp16 + ldmatrix + cp.async.
// ---------------------------------------------------------------------------
#define RSW   36
#define AWSZ  (128 * RSW)
#define WWSZ  (192 * RSW)
#define GEMM_SMEM ((2 * AWSZ + 2 * WWSZ) * 4)   // 92160 bytes

template<int NCTOT, bool AHALF, bool OHALF>
__global__ __launch_bounds__(512)
void gemm_mma(const void* __restrict__ Ain, const __half* __restrict__ Wh,
              const float* __restrict__ bias, void* __restrict__ outv,
              float outScale)
{
    extern __shared__ uint32_t smw[];
    const uint32_t smb = smem_u32(smw);
    const int tid  = threadIdx.x;
    const int wid  = tid >> 5;
    const int lane = tid & 31;
    const int wm   = wid & 3;
    const int wn   = wid >> 2;
    const int gid  = lane >> 2;
    const int tc   = lane & 3;

    const size_t mbase = (size_t)blockIdx.x * 128;
    const int    nbase = blockIdx.y * 192;
    const float*  Af = (const float*)Ain + mbase * CDIM;
    const __half* Ah = (const __half*)Ain + mbase * CDIM;
    const __half* Wblk = Wh + (size_t)nbase * CDIM;

    const uint32_t stA[2] = { smb, smb + AWSZ * 4 };
    const uint32_t stW[2] = { smb + 2 * AWSZ * 4, smb + (2 * AWSZ + WWSZ) * 4 };

    float acc[2][6][4];
#pragma unroll
    for (int mi = 0; mi < 2; mi++)
#pragma unroll
        for (int ni = 0; ni < 6; ni++)
#pragma unroll
            for (int j = 0; j < 4; j++) acc[mi][ni][j] = 0.f;

    const int prow = tid >> 2;
    const int psub = tid & 3;
    float4 apf[4];

    auto issueW = [&](int c, int st) {
        const int ko = c * 64;
#pragma unroll
        for (int k = 0; k < 3; k++) {
            const int i = tid + k * 512;
            const int r = i >> 3, g = i & 7;
            cp16(stW[st] + (uint32_t)(r * RSW + g * 4) * 4, Wblk + (size_t)r * CDIM + ko + g * 8);
        }
    };
    auto issueA_h = [&](int c, int st) {
        const int ko = c * 64;
        cp16(stA[st] + (uint32_t)(prow * RSW + psub * 4) * 4,
             Ah + (size_t)prow * CDIM + ko + psub * 8);
        cp16(stA[st] + (uint32_t)(prow * RSW + (psub + 4) * 4) * 4,
             Ah + (size_t)prow * CDIM + ko + (psub + 4) * 8);
    };
    auto ldgA_f = [&](int c) {
        const int ko = c * 64 + psub * 16;
#pragma unroll
        for (int j = 0; j < 4; j++)
            apf[j] = *(const float4*)(Af + (size_t)prow * CDIM + ko + j * 4);
    };
    auto stsA_f = [&](int st) {
        uint32_t* sA = smw + (stA[st] - smb) / 4;
#pragma unroll
        for (int j = 0; j < 4; j++) {
            uint2 p = { h2u(apf[j].x, apf[j].y), h2u(apf[j].z, apf[j].w) };
            *(uint2*)&sA[prow * RSW + psub * 8 + j * 2] = p;
        }
    };

    if (AHALF) { issueA_h(0, 0); } else { ldgA_f(0); }
    issueW(0, 0);
    asm volatile("cp.async.commit_group;" ::: "memory");
    if (!AHALF) stsA_f(0);
    asm volatile("cp.async.wait_group 0;" ::: "memory");
    __syncthreads();

    const uint32_t a_lane = ((uint32_t)(wm * 32 + ((lane >> 3) & 1) * 8 + (lane & 7)) * RSW
                            + (lane >> 4) * 4) * 4;
    const uint32_t b_lane = ((uint32_t)(wn * 48 + (lane >> 4) * 8 + (lane & 7)) * RSW
                            + ((lane >> 3) & 1) * 4) * 4;

#pragma unroll 1
    for (int c = 0; c < 3; c++) {
        const int st = c & 1;
        if (c < 2) {
            if (AHALF) issueA_h(c + 1, st ^ 1); else ldgA_f(c + 1);
            issueW(c + 1, st ^ 1);
            asm volatile("cp.async.commit_group;" ::: "memory");
        }
#pragma unroll
        for (int t = 0; t < 4; t++) {
            uint32_t a[2][4], bb[3][4];
#pragma unroll
            for (int mi = 0; mi < 2; mi++)
                ldsm4(a[mi], stA[st] + a_lane + (uint32_t)(mi * 16 * RSW + t * 8) * 4);
#pragma unroll
            for (int p = 0; p < 3; p++)
                ldsm4(bb[p], stW[st] + b_lane + (uint32_t)(p * 16 * RSW + t * 8) * 4);
#pragma unroll
            for (int p = 0; p < 3; p++) {
                mma_f16(acc[0][2 * p],     a[0], bb[p][0], bb[p][1]);
                mma_f16(acc[1][2 * p],     a[1], bb[p][0], bb[p][1]);
                mma_f16(acc[0][2 * p + 1], a[0], bb[p][2], bb[p][3]);
                mma_f16(acc[1][2 * p + 1], a[1], bb[p][2], bb[p][3]);
            }
        }
        if (c < 2) {
            if (!AHALF) stsA_f(st ^ 1);
            asm volatile("cp.async.wait_group 0;" ::: "memory");
            __syncthreads();
        }
    }

#pragma unroll
    for (int mi = 0; mi < 2; mi++) {
#pragma unroll
        for (int ni = 0; ni < 6; ni++) {
            const size_t row = mbase + wm * 32 + mi * 16 + gid;
            const int    col = nbase + wn * 48 + ni * 8 + tc * 2;
            const float2 bb2 = *(const float2*)&bias[col];
            float v0 = (acc[mi][ni][0] + bb2.x) * outScale;
            float v1 = (acc[mi][ni][1] + bb2.y) * outScale;
            float v2 = (acc[mi][ni][2] + bb2.x) * outScale;
            float v3 = (acc[mi][ni][3] + bb2.y) * outScale;
            if (OHALF) {
                __half* o = (__half*)outv;
                *(uint32_t*)&o[(row    ) * NCTOT + col] = h2u(v0, v1);
                *(uint32_t*)&o[(row + 8) * NCTOT + col] = h2u(v2, v3);
            } else {
                float* o = (float*)outv;
                float2 r0 = {v0, v1}, r1 = {v2, v3};
                *(float2*)&o[(row    ) * NCTOT + col] = r0;
                *(float2*)&o[(row + 8) * NCTOT + col] = r1;
            }
        }
    }
}

// ---------------------------------------------------------------------------
// fp16 attention, fully ldmatrix-based: 2 heads/CTA, warp-local.
// Q/K/V stored as raw token rows (stride 20 words); pad rows zeroed
// (Q,V -> 64 rows, K -> 56 rows) so out-of-range tiles read zeros.
// QK: A via ldsm4, B(K) via ldsm4/ldsm2 (no-trans; same tile pattern as A).
// PV: B(V^T) via ldsm4.trans directly on V rows -- no transpose scatter.
// Register-resident softmax (R14) unchanged.
// ---------------------------------------------------------------------------
#define HPC     2
#define TSTR    20                                // words per token row
#define OFF_K   (64 * TSTR)                       // 1280
#define OFF_V   (OFF_K + 56 * TSTR)               // 2400
#define OFF_RPB (OFF_V + 64 * TSTR)               // 3680
#define HEADW   (OFF_RPB + 172)                   // 3852 words (16B-aligned)
#define ATTN_SMEM (HPC * HEADW * 4)               // 30816 bytes

__global__ __launch_bounds__(HPC * 32)
void attn_mma(const __half* __restrict__ Q, const __half* __restrict__ KV,
              const float* __restrict__ rpb, __half* __restrict__ O)
{
    extern __shared__ uint32_t smw[];
    const int wid  = threadIdx.x >> 5;
    const int lane = threadIdx.x & 31;
    const int gid  = lane >> 2;
    const int tc   = lane & 3;
    const int bt   = blockIdx.x;
    const int b    = bt >> 1;
    const int h    = blockIdx.y * HPC + wid;

    uint32_t* sQ  = smw + wid * HEADW;
    uint32_t* sK  = sQ + OFF_K;
    uint32_t* sV  = sQ + OFF_V;
    float*    srpb = (float*)(sQ + OFF_RPB);
    const uint32_t sQb = smem_u32(sQ);
    const uint32_t sKb = smem_u32(sK);
    const uint32_t sVb = smem_u32(sV);

    for (int i = lane; i < 169; i += 32) srpb[i] = rpb[i * NHEAD + h];

    // Zero pad rows (rows 49.. of each region; 16B stores, 980%4==0)
    const uint4 z4 = {0u, 0u, 0u, 0u};
#pragma unroll
    for (int i = lane; i < 75; i += 32) *(uint4*)&sQ[980 + i * 4] = z4;
#pragma unroll
    for (int i = lane; i < 35; i += 32) *(uint4*)&sK[980 + i * 4] = z4;
#pragma unroll
    for (int i = lane; i < 75; i += 32) *(uint4*)&sV[980 + i * 4] = z4;

    // Load Q, K, V token rows (raw uint4 copies)
    for (int i = lane; i < NTOK * 4; i += 32) {
        const int n = i >> 2, g = i & 3;
        *(uint4*)&sQ[n * TSTR + g * 4] =
            *(const uint4*)&Q[((size_t)(b * NTOK + n)) * CDIM + h * HDIM + g * 8];
        const size_t kb = (size_t)(bt * NTOK + n) * (2 * CDIM) + h * HDIM + g * 8;
        *(uint4*)&sK[n * TSTR + g * 4] = *(const uint4*)&KV[kb];
        *(uint4*)&sV[n * TSTR + g * 4] = *(const uint4*)&KV[kb + CDIM];
    }
    __syncwarp();

    // ---- S = Q K^T (scale pre-folded into Q) ----
    float sf[4][7][4];
#pragma unroll
    for (int mi = 0; mi < 4; mi++)
#pragma unroll
        for (int ni = 0; ni < 7; ni++)
#pragma unroll
            for (int j = 0; j < 4; j++) sf[mi][ni][j] = 0.f;

    const int l15 = lane & 15, l7 = lane & 7;
    const int g16 = lane >> 4, g8 = (lane >> 3) & 1;

#pragma unroll
    for (int t = 0; t < 2; t++) {
        uint32_t a[4][4];
#pragma unroll
        for (int mi = 0; mi < 4; mi++)
            ldsm4(a[mi], sQb + (uint32_t)((16 * mi + l15) * TSTR + t * 8 + g16 * 4) * 4);
        uint32_t bb[4][4];
#pragma unroll
        for (int p = 0; p < 3; p++)
            ldsm4(bb[p], sKb + (uint32_t)((8 * (2 * p + g16) + l7) * TSTR + t * 8 + g8 * 4) * 4);
        ldsm2(bb[3], sKb + (uint32_t)((48 + l7) * TSTR + t * 8 + g8 * 4) * 4);
#pragma unroll
        for (int p = 0; p < 3; p++)
#pragma unroll
            for (int mi = 0; mi < 4; mi++) {
                mma_f16(sf[mi][2 * p],     a[mi], bb[p][0], bb[p][1]);
                mma_f16(sf[mi][2 * p + 1], a[mi], bb[p][2], bb[p][3]);
            }
#pragma unroll
        for (int mi = 0; mi < 4; mi++)
            mma_f16(sf[mi][6], a[mi], bb[3][0], bb[3][1]);
    }

    // ---- register softmax + pack to PV A-fragments ----
    uint32_t pf[4][4][4];
#pragma unroll
    for (int mi = 0; mi < 4; mi++) {
#pragma unroll
        for (int jp = 0; jp < 2; jp++) {
            const int n = 16 * mi + 8 * jp + gid;
            const bool vrow = (n < NTOK);
            const int fn = 13 * (n / 7) + (n % 7);
            float vv[7][2];
            float mx = -1e30f;
#pragma unroll
            for (int ni = 0; ni < 7; ni++) {
#pragma unroll
                for (int jc = 0; jc < 2; jc++) {
                    const int m = 8 * ni + 2 * tc + jc;
                    float v = sf[mi][ni][jp * 2 + jc];
                    if (vrow && m < NTOK) {
                        const int fm = 13 * (m / 7) + (m % 7);
                        v += srpb[fn - fm + 84];
                    } else {
                        v = -1e30f;
                    }
                    vv[ni][jc] = v;
                    mx = fmaxf(mx, v);
                }
            }
            mx = fmaxf(mx, __shfl_xor_sync(0xffffffffu, mx, 1));
            mx = fmaxf(mx, __shfl_xor_sync(0xffffffffu, mx, 2));
            float sum = 0.f;
#pragma unroll
            for (int ni = 0; ni < 7; ni++)
#pragma unroll
                for (int jc = 0; jc < 2; jc++) {
                    float e = __expf(vv[ni][jc] - mx);
                    vv[ni][jc] = e;
                    sum += e;
                }
            sum += __shfl_xor_sync(0xffffffffu, sum, 1);
            sum += __shfl_xor_sync(0xffffffffu, sum, 2);
            const float inv = vrow ? (1.f / sum) : 0.f;
#pragma unroll
            for (int t = 0; t < 4; t++) {
                pf[mi][t][jp] = h2u(vv[2 * t][0] * inv, vv[2 * t][1] * inv);
                pf[mi][t][2 + jp] = (2 * t + 1 < 7)
                    ? h2u(vv[2 * t + 1][0] * inv, vv[2 * t + 1][1] * inv) : 0u;
            }
        }
    }

    // ---- O = P V: B = V^T via ldsm4.trans on raw V rows ----
    float of[4][4][4];
#pragma unroll
    for (int mi = 0; mi < 4; mi++)
#pragma unroll
        for (int nd = 0; nd < 4; nd++)
#pragma unroll
            for (int j = 0; j < 4; j++) of[mi][nd][j] = 0.f;

#pragma unroll
    for (int t = 0; t < 4; t++) {
        uint32_t bb[2][4];
#pragma unroll
        for (int q = 0; q < 2; q++)
            ldsm4t(bb[q], sVb + (uint32_t)((t * 16 + g8 * 8 + l7) * TSTR + (2 * q + g16) * 4) * 4);
#pragma unroll
        for (int q = 0; q < 2; q++)
#pragma unroll
            for (int mi = 0; mi < 4; mi++) {
                mma_f16(of[mi][2 * q],     pf[mi][t], bb[q][0], bb[q][1]);
                mma_f16(of[mi][2 * q + 1], pf[mi][t], bb[q][2], bb[q][3]);
            }
    }

    // Store O head slice (half2 words)
#pragma unroll
    for (int mi = 0; mi < 4; mi++) {
        const int r0 = 16 * mi + gid;
#pragma unroll
        for (int nd = 0; nd < 4; nd++) {
            const int col = h * HDIM + nd * 8 + 2 * tc;
            if (r0 < NTOK)
                *(uint32_t*)&O[((size_t)(bt * NTOK + r0)) * CDIM + col] =
                    h2u(of[mi][nd][0], of[mi][nd][1]);
            if (r0 + 8 < NTOK)
                *(uint32_t*)&O[((size_t)(bt * NTOK + r0 + 8)) * CDIM + col] =
                    h2u(of[mi][nd][2], of[mi][nd][3]);
        }
    }
}

// ---------------------------------------------------------------------------
// kernel_launch
// ---------------------------------------------------------------------------
extern "C" void kernel_launch(void* const* d_in, const int* in_sizes, int n_in,
                              void* d_out, int out_size)
{
    const float* x      = (const float*)d_in[0];
    const float* memory = (const float*)d_in[1];
    const float* w_q    = (const float*)d_in[2];
    const float* b_q    = (const float*)d_in[3];
    const float* w_kv   = (const float*)d_in[4];
    const float* b_kv   = (const float*)d_in[5];
    const float* w_proj = (const float*)d_in[6];
    const float* b_proj = (const float*)d_in[7];
    const float* rpb    = (const float*)d_in[8];

    __half *gq, *gkv, *gao, *wq16, *wkv16, *wp16;
    cudaGetSymbolAddress((void**)&gq,    g_q);
    cudaGetSymbolAddress((void**)&gkv,   g_kv);
    cudaGetSymbolAddress((void**)&gao,   g_ao);
    cudaGetSymbolAddress((void**)&wq16,  g_wq16);
    cudaGetSymbolAddress((void**)&wkv16, g_wkv16);
    cudaGetSymbolAddress((void**)&wp16,  g_wp16);

    cudaFuncSetAttribute((const void*)gemm_mma<192, false, true>,
                         cudaFuncAttributeMaxDynamicSharedMemorySize, GEMM_SMEM);
    cudaFuncSetAttribute((const void*)gemm_mma<384, false, true>,
                         cudaFuncAttributeMaxDynamicSharedMemorySize, GEMM_SMEM);
    cudaFuncSetAttribute((const void*)gemm_mma<192, true, false>,
                         cudaFuncAttributeMaxDynamicSharedMemorySize, GEMM_SMEM);
    cudaFuncSetAttribute((const void*)attn_mma,
                         cudaFuncAttributeMaxDynamicSharedMemorySize, ATTN_SMEM);

    const float scale = 0.17677669529663687f;   // 32^-0.5, folded into Q

    cvt_w<<<(2 * CDIM * CDIM + 255) / 256, 256>>>(w_q, w_kv, w_proj);

    gemm_mma<192, false, true><<<dim3(M_Q / 128, 1), 512, GEMM_SMEM>>>(
        x, wq16, b_q, gq, scale);
    gemm_mma<384, false, true><<<dim3(M_KV / 128, 2), 512, GEMM_SMEM>>>(
        memory, wkv16, b_kv, gkv, 1.0f);
    attn_mma<<<dim3(BATCH * TT, NHEAD / HPC), HPC * 32, ATTN_SMEM>>>(
        gq, gkv, rpb, gao);
    gemm_mma<192, true, false><<<dim3(M_KV / 128, 1), 512, GEMM_SMEM>>>(
        gao, wp16, b_proj, d_out, 1.0f);
}